// round 1
// baseline (speedup 1.0000x reference)
#include <cuda_runtime.h>

// Problem constants
#define S_LEN 2048
#define D_DIM 1024
#define NB    4
#define NH    16
#define DHD   64
#define M_ROWS (NB * S_LEN)   // 8192

// Scratch (device globals: allocation-free per harness rules)
__device__ float g_Q [M_ROWS * D_DIM];
__device__ float g_K [M_ROWS * D_DIM];
__device__ float g_V [M_ROWS * D_DIM];
__device__ float g_AO[M_ROWS * D_DIM];

// ---------------------------------------------------------------------------
// NT GEMM: C[m,n] = sum_k A[m,k] * B[n,k]
// A: [M,K] row-major, B: [N,K] row-major, C: [M,N] row-major.
// 64x64 block tile, 16 k-slice, 256 threads, 4x4 per thread (interleaved).
// ---------------------------------------------------------------------------
__global__ void __launch_bounds__(256) gemm_nt(const float* __restrict__ A,
                                               const float* __restrict__ B,
                                               float* __restrict__ C,
                                               int M, int N, int K) {
    __shared__ float As[16][65];   // As[k][m] padded: conflict-free
    __shared__ float Bs[16][65];   // Bs[k][n]

    const int bm = blockIdx.y * 64;
    const int bn = blockIdx.x * 64;
    const int tid = threadIdx.x;
    const int tx = tid & 15;
    const int ty = tid >> 4;

    const float* Ab = A + (size_t)bm * K;
    const float* Bb = B + (size_t)bn * K;

    float acc[4][4];
#pragma unroll
    for (int i = 0; i < 4; i++)
#pragma unroll
        for (int j = 0; j < 4; j++) acc[i][j] = 0.0f;

    for (int k0 = 0; k0 < K; k0 += 16) {
        // Load 64 rows x 16 k of both A and B tiles (coalesced along k)
        const int kk = tid & 15;
        const int r0 = tid >> 4;
#pragma unroll
        for (int i = 0; i < 4; i++) {
            int r = r0 + i * 16;
            As[kk][r] = Ab[(size_t)r * K + k0 + kk];
            Bs[kk][r] = Bb[(size_t)r * K + k0 + kk];
        }
        __syncthreads();

#pragma unroll
        for (int k = 0; k < 16; k++) {
            float a[4], b[4];
#pragma unroll
            for (int i = 0; i < 4; i++) a[i] = As[k][ty + 16 * i];
#pragma unroll
            for (int j = 0; j < 4; j++) b[j] = Bs[k][tx + 16 * j];
#pragma unroll
            for (int i = 0; i < 4; i++)
#pragma unroll
                for (int j = 0; j < 4; j++) acc[i][j] += a[i] * b[j];
        }
        __syncthreads();
    }

#pragma unroll
    for (int i = 0; i < 4; i++)
#pragma unroll
        for (int j = 0; j < 4; j++)
            C[(size_t)(bm + ty + 16 * i) * N + (bn + tx + 16 * j)] = acc[i][j];
}

// ---------------------------------------------------------------------------
// Causal flash attention (fp32, online softmax).
// Grid: (S/64 q-tiles, B*H). Block: 256 threads (16x16), 4x4 register tiles.
// Q/K/V layout: [b*S + s][h*64 + dh] (stride D_DIM).
// Shared: Qs (64x65), KVs (64x65, reused K->V), Ps (64x65) — dynamic.
// ---------------------------------------------------------------------------
#define TPAD 65
#define SMEM_ATTN (3 * 64 * TPAD * (int)sizeof(float))

__global__ void __launch_bounds__(256) attn_kernel(const float* __restrict__ Q,
                                                   const float* __restrict__ K,
                                                   const float* __restrict__ V,
                                                   float* __restrict__ O) {
    extern __shared__ float sm[];
    float* Qs  = sm;
    float* KVs = sm + 64 * TPAD;
    float* Ps  = sm + 2 * 64 * TPAD;

    const int bh = blockIdx.y;
    const int b  = bh >> 4;
    const int h  = bh & 15;
    const int q0 = blockIdx.x * 64;

    const int tid = threadIdx.x;
    const int tx = tid & 15;
    const int ty = tid >> 4;

    const size_t base = ((size_t)b * S_LEN) * D_DIM + (size_t)h * DHD;

    // Load Q tile
    for (int idx = tid; idx < 64 * 64; idx += 256) {
        int r = idx >> 6, c = idx & 63;
        Qs[r * TPAD + c] = Q[base + (size_t)(q0 + r) * D_DIM + c];
    }

    float m_i[4], l_i[4], o[4][4];
#pragma unroll
    for (int i = 0; i < 4; i++) {
        m_i[i] = -1e30f;
        l_i[i] = 0.0f;
#pragma unroll
        for (int j = 0; j < 4; j++) o[i][j] = 0.0f;
    }
    const float scale = 0.125f;   // 1/sqrt(64)

    __syncthreads();

    for (int kv0 = 0; kv0 <= q0; kv0 += 64) {
        // ---- Load K tile ----
        for (int idx = tid; idx < 64 * 64; idx += 256) {
            int r = idx >> 6, c = idx & 63;
            KVs[r * TPAD + c] = K[base + (size_t)(kv0 + r) * D_DIM + c];
        }
        __syncthreads();

        // ---- Scores S = Q K^T (4x4 per thread) ----
        float s[4][4];
#pragma unroll
        for (int i = 0; i < 4; i++)
#pragma unroll
            for (int j = 0; j < 4; j++) s[i][j] = 0.0f;

#pragma unroll 8
        for (int d = 0; d < 64; d++) {
            float a[4], bb[4];
#pragma unroll
            for (int i = 0; i < 4; i++) a[i]  = Qs[(ty + 16 * i) * TPAD + d];
#pragma unroll
            for (int j = 0; j < 4; j++) bb[j] = KVs[(tx + 16 * j) * TPAD + d];
#pragma unroll
            for (int i = 0; i < 4; i++)
#pragma unroll
                for (int j = 0; j < 4; j++) s[i][j] += a[i] * bb[j];
        }

        // ---- Scale + causal mask (only diagonal tile can mask) ----
        const bool diag = (kv0 == q0);
#pragma unroll
        for (int i = 0; i < 4; i++) {
            int qg = q0 + ty + 16 * i;
#pragma unroll
            for (int j = 0; j < 4; j++) {
                int kg = kv0 + tx + 16 * j;
                float v = s[i][j] * scale;
                if (diag && kg > qg) v = -1e30f;
                s[i][j] = v;
            }
        }

        // ---- Online softmax (row groups of 16 threads share a warp half) ----
#pragma unroll
        for (int i = 0; i < 4; i++) {
            float mt = fmaxf(fmaxf(s[i][0], s[i][1]), fmaxf(s[i][2], s[i][3]));
#pragma unroll
            for (int off = 8; off > 0; off >>= 1)
                mt = fmaxf(mt, __shfl_xor_sync(0xffffffffu, mt, off, 16));
            float mn = fmaxf(m_i[i], mt);
            float corr = __expf(m_i[i] - mn);
            m_i[i] = mn;

            float lt = 0.0f;
#pragma unroll
            for (int j = 0; j < 4; j++) {
                s[i][j] = __expf(s[i][j] - mn);
                lt += s[i][j];
            }
#pragma unroll
            for (int off = 8; off > 0; off >>= 1)
                lt += __shfl_xor_sync(0xffffffffu, lt, off, 16);
            l_i[i] = l_i[i] * corr + lt;

#pragma unroll
            for (int j = 0; j < 4; j++) {
                o[i][j] *= corr;
                Ps[(ty + 16 * i) * TPAD + (tx + 16 * j)] = s[i][j];
            }
        }
        __syncthreads();   // Ps written; everyone done with K tile

        // ---- Load V tile (reuse KVs) ----
        for (int idx = tid; idx < 64 * 64; idx += 256) {
            int r = idx >> 6, c = idx & 63;
            KVs[r * TPAD + c] = V[base + (size_t)(kv0 + r) * D_DIM + c];
        }
        __syncthreads();

        // ---- O += P @ V ----
#pragma unroll 8
        for (int k = 0; k < 64; k++) {
            float p[4], vv[4];
#pragma unroll
            for (int i = 0; i < 4; i++) p[i]  = Ps[(ty + 16 * i) * TPAD + k];
#pragma unroll
            for (int j = 0; j < 4; j++) vv[j] = KVs[k * TPAD + (tx + 16 * j)];
#pragma unroll
            for (int i = 0; i < 4; i++)
#pragma unroll
                for (int j = 0; j < 4; j++) o[i][j] += p[i] * vv[j];
        }
        __syncthreads();   // done with Ps/KVs before next iteration
    }

    // ---- Normalize & write (layout [b*S+s][h*64+dh]) ----
#pragma unroll
    for (int i = 0; i < 4; i++) {
        float inv_l = 1.0f / l_i[i];
#pragma unroll
        for (int j = 0; j < 4; j++)
            O[base + (size_t)(q0 + ty + 16 * i) * D_DIM + (tx + 16 * j)] =
                o[i][j] * inv_l;
    }
}

// ---------------------------------------------------------------------------
extern "C" void kernel_launch(void* const* d_in, const int* in_sizes, int n_in,
                              void* d_out, int out_size) {
    const float* x  = (const float*)d_in[0];
    const float* wq = (const float*)d_in[1];
    const float* wk = (const float*)d_in[2];
    const float* wv = (const float*)d_in[3];
    const float* wo = (const float*)d_in[4];
    float* out = (float*)d_out;

    float *Qp, *Kp, *Vp, *AOp;
    cudaGetSymbolAddress((void**)&Qp,  g_Q);
    cudaGetSymbolAddress((void**)&Kp,  g_K);
    cudaGetSymbolAddress((void**)&Vp,  g_V);
    cudaGetSymbolAddress((void**)&AOp, g_AO);

    dim3 gemm_grid(D_DIM / 64, M_ROWS / 64);   // (16, 128)
    gemm_nt<<<gemm_grid, 256>>>(x, wq, Qp, M_ROWS, D_DIM, D_DIM);
    gemm_nt<<<gemm_grid, 256>>>(x, wk, Kp, M_ROWS, D_DIM, D_DIM);
    gemm_nt<<<gemm_grid, 256>>>(x, wv, Vp, M_ROWS, D_DIM, D_DIM);

    cudaFuncSetAttribute(attn_kernel,
                         cudaFuncAttributeMaxDynamicSharedMemorySize,
                         SMEM_ATTN);
    attn_kernel<<<dim3(S_LEN / 64, NB * NH), 256, SMEM_ATTN>>>(Qp, Kp, Vp, AOp);

    gemm_nt<<<gemm_grid, 256>>>(AOp, wo, out, M_ROWS, D_DIM, D_DIM);
}

// round 3
// speedup vs baseline: 1.8757x; 1.8757x over previous
#include <cuda_runtime.h>
#include <cstdint>

// Problem constants
#define S_LEN 2048
#define D_DIM 1024
#define NB    4
#define NH    16
#define DHD   64
#define M_ROWS (NB * S_LEN)   // 8192

// Scratch (device globals: allocation-free per harness rules)
__device__ float g_Q [M_ROWS * D_DIM];
__device__ float g_K [M_ROWS * D_DIM];
__device__ float g_V [M_ROWS * D_DIM];
__device__ float g_AO[M_ROWS * D_DIM];

// ===========================================================================
// tf32 helpers (legacy mma.sync path — tcgen05 is rejected by this build's
// ptxas target, so the HMMA pipeline is the available tensor path)
// ===========================================================================
__device__ __forceinline__ uint32_t f2tf32(float f) {
    uint32_t u;
    asm("cvt.rna.tf32.f32 %0, %1;" : "=r"(u) : "f"(f));
    return u;
}

__device__ __forceinline__ void mma_tf32(float c[4], const uint32_t a[4],
                                         const uint32_t b[2]) {
    asm volatile(
        "mma.sync.aligned.m16n8k8.row.col.f32.tf32.tf32.f32 "
        "{%0,%1,%2,%3}, {%4,%5,%6,%7}, {%8,%9}, {%0,%1,%2,%3};"
        : "+f"(c[0]), "+f"(c[1]), "+f"(c[2]), "+f"(c[3])
        : "r"(a[0]), "r"(a[1]), "r"(a[2]), "r"(a[3]), "r"(b[0]), "r"(b[1]));
}

// ===========================================================================
// NT GEMM via tf32 mma.sync: C[m,n] = sum_k A[m,k] * B[n,k]
// 128x128 CTA tile, 256 threads (8 warps, 2Mx4N), warp tile 64x32.
// K chunk = 32, register-prefetch double buffering.
// smem [row][k] stride 36: fragment LDS pattern (4g+t mod 32) conflict-free.
// ===========================================================================
#define KC     32
#define SSTR   36
#define TILEW  (128 * SSTR)   // floats per tile

__global__ void __launch_bounds__(256) gemm_mma(const float* __restrict__ A,
                                                const float* __restrict__ B,
                                                float* __restrict__ C,
                                                int M, int N, int K) {
    __shared__ float As[128 * SSTR];
    __shared__ float Bs[128 * SSTR];

    const int tid  = threadIdx.x;
    const int lane = tid & 31;
    const int wid  = tid >> 5;
    const int g    = lane >> 2;     // group id (0..7)
    const int t    = lane & 3;      // thread-in-group (0..3)
    const int wm   = (wid & 1) * 64;   // warp M offset
    const int wn   = (wid >> 1) * 32;  // warp N offset

    const int bm = blockIdx.y * 128;
    const int bn = blockIdx.x * 128;

    // Global load mapping: each thread loads 4 float4 from A and 4 from B per chunk
    const int c4  = tid & 7;        // float4 slot within 32-k row
    const int lr  = tid >> 3;       // 0..31 base row
    const float* Ag = A + (size_t)(bm + lr) * K + c4 * 4;
    const float* Bg = B + (size_t)(bn + lr) * K + c4 * 4;

    float acc[4][4][4];
#pragma unroll
    for (int i = 0; i < 4; i++)
#pragma unroll
        for (int j = 0; j < 4; j++)
#pragma unroll
            for (int q = 0; q < 4; q++) acc[i][j][q] = 0.0f;

    const int CHUNKS = K / KC;      // 32
    float4 pa[4], pb[4];

    // Prologue: load chunk 0
#pragma unroll
    for (int i = 0; i < 4; i++) {
        pa[i] = *(const float4*)(Ag + (size_t)(i * 32) * K);
        pb[i] = *(const float4*)(Bg + (size_t)(i * 32) * K);
    }

    for (int c = 0; c < CHUNKS; c++) {
        // Store prefetched chunk to smem (tf32-rounded)
#pragma unroll
        for (int i = 0; i < 4; i++) {
            const int row = lr + i * 32;
            uint32_t* as = (uint32_t*)&As[row * SSTR + c4 * 4];
            uint32_t* bs = (uint32_t*)&Bs[row * SSTR + c4 * 4];
            as[0] = f2tf32(pa[i].x); as[1] = f2tf32(pa[i].y);
            as[2] = f2tf32(pa[i].z); as[3] = f2tf32(pa[i].w);
            bs[0] = f2tf32(pb[i].x); bs[1] = f2tf32(pb[i].y);
            bs[2] = f2tf32(pb[i].z); bs[3] = f2tf32(pb[i].w);
        }
        __syncthreads();

        // Prefetch next chunk
        if (c + 1 < CHUNKS) {
            const float* Agn = Ag + (c + 1) * KC;
            const float* Bgn = Bg + (c + 1) * KC;
#pragma unroll
            for (int i = 0; i < 4; i++) {
                pa[i] = *(const float4*)(Agn + (size_t)(i * 32) * K);
                pb[i] = *(const float4*)(Bgn + (size_t)(i * 32) * K);
            }
        }

        // Compute: 4 k8-steps
        const uint32_t* Asu = (const uint32_t*)As;
        const uint32_t* Bsu = (const uint32_t*)Bs;
#pragma unroll
        for (int s = 0; s < 4; s++) {
            const int kb = s * 8;
            uint32_t af[4][4], bf[4][2];
#pragma unroll
            for (int im = 0; im < 4; im++) {
                const int r = wm + im * 16 + g;
                af[im][0] = Asu[r * SSTR + kb + t];
                af[im][1] = Asu[(r + 8) * SSTR + kb + t];
                af[im][2] = Asu[r * SSTR + kb + t + 4];
                af[im][3] = Asu[(r + 8) * SSTR + kb + t + 4];
            }
#pragma unroll
            for (int jn = 0; jn < 4; jn++) {
                const int n = wn + jn * 8 + g;
                bf[jn][0] = Bsu[n * SSTR + kb + t];
                bf[jn][1] = Bsu[n * SSTR + kb + t + 4];
            }
#pragma unroll
            for (int im = 0; im < 4; im++)
#pragma unroll
                for (int jn = 0; jn < 4; jn++)
                    mma_tf32(acc[im][jn], af[im], bf[jn]);
        }
        __syncthreads();
    }

    // Epilogue: direct register -> global (float2 stores)
#pragma unroll
    for (int im = 0; im < 4; im++) {
#pragma unroll
        for (int jn = 0; jn < 4; jn++) {
            const int row = bm + wm + im * 16 + g;
            const int col = bn + wn + jn * 8 + 2 * t;
            *(float2*)(C + (size_t)row * N + col) =
                make_float2(acc[im][jn][0], acc[im][jn][1]);
            *(float2*)(C + (size_t)(row + 8) * N + col) =
                make_float2(acc[im][jn][2], acc[im][jn][3]);
        }
    }
}

// ===========================================================================
// Causal flash attention (fp32, online softmax) — unchanged from R1 baseline
// ===========================================================================
#define TPAD 65
#define SMEM_ATTN (3 * 64 * TPAD * (int)sizeof(float))

__global__ void __launch_bounds__(256) attn_kernel(const float* __restrict__ Q,
                                                   const float* __restrict__ K,
                                                   const float* __restrict__ V,
                                                   float* __restrict__ O) {
    extern __shared__ float smf[];
    float* Qs  = smf;
    float* KVs = smf + 64 * TPAD;
    float* Ps  = smf + 2 * 64 * TPAD;

    const int bh = blockIdx.y;
    const int b  = bh >> 4;
    const int h  = bh & 15;
    const int q0 = blockIdx.x * 64;

    const int tid = threadIdx.x;
    const int tx = tid & 15;
    const int ty = tid >> 4;

    const size_t base = ((size_t)b * S_LEN) * D_DIM + (size_t)h * DHD;

    for (int idx = tid; idx < 64 * 64; idx += 256) {
        int r = idx >> 6, c = idx & 63;
        Qs[r * TPAD + c] = Q[base + (size_t)(q0 + r) * D_DIM + c];
    }

    float m_i[4], l_i[4], o[4][4];
#pragma unroll
    for (int i = 0; i < 4; i++) {
        m_i[i] = -1e30f;
        l_i[i] = 0.0f;
#pragma unroll
        for (int j = 0; j < 4; j++) o[i][j] = 0.0f;
    }
    const float scale = 0.125f;

    __syncthreads();

    for (int kv0 = 0; kv0 <= q0; kv0 += 64) {
        for (int idx = tid; idx < 64 * 64; idx += 256) {
            int r = idx >> 6, c = idx & 63;
            KVs[r * TPAD + c] = K[base + (size_t)(kv0 + r) * D_DIM + c];
        }
        __syncthreads();

        float s[4][4];
#pragma unroll
        for (int i = 0; i < 4; i++)
#pragma unroll
            for (int j = 0; j < 4; j++) s[i][j] = 0.0f;

#pragma unroll 8
        for (int d = 0; d < 64; d++) {
            float a[4], bb[4];
#pragma unroll
            for (int i = 0; i < 4; i++) a[i]  = Qs[(ty + 16 * i) * TPAD + d];
#pragma unroll
            for (int j = 0; j < 4; j++) bb[j] = KVs[(tx + 16 * j) * TPAD + d];
#pragma unroll
            for (int i = 0; i < 4; i++)
#pragma unroll
                for (int j = 0; j < 4; j++) s[i][j] += a[i] * bb[j];
        }

        const bool diag = (kv0 == q0);
#pragma unroll
        for (int i = 0; i < 4; i++) {
            int qg = q0 + ty + 16 * i;
#pragma unroll
            for (int j = 0; j < 4; j++) {
                int kg = kv0 + tx + 16 * j;
                float v = s[i][j] * scale;
                if (diag && kg > qg) v = -1e30f;
                s[i][j] = v;
            }
        }

#pragma unroll
        for (int i = 0; i < 4; i++) {
            float mt = fmaxf(fmaxf(s[i][0], s[i][1]), fmaxf(s[i][2], s[i][3]));
#pragma unroll
            for (int off = 8; off > 0; off >>= 1)
                mt = fmaxf(mt, __shfl_xor_sync(0xffffffffu, mt, off, 16));
            float mn = fmaxf(m_i[i], mt);
            float corr = __expf(m_i[i] - mn);
            m_i[i] = mn;

            float lt = 0.0f;
#pragma unroll
            for (int j = 0; j < 4; j++) {
                s[i][j] = __expf(s[i][j] - mn);
                lt += s[i][j];
            }
#pragma unroll
            for (int off = 8; off > 0; off >>= 1)
                lt += __shfl_xor_sync(0xffffffffu, lt, off, 16);
            l_i[i] = l_i[i] * corr + lt;

#pragma unroll
            for (int j = 0; j < 4; j++) {
                o[i][j] *= corr;
                Ps[(ty + 16 * i) * TPAD + (tx + 16 * j)] = s[i][j];
            }
        }
        __syncthreads();

        for (int idx = tid; idx < 64 * 64; idx += 256) {
            int r = idx >> 6, c = idx & 63;
            KVs[r * TPAD + c] = V[base + (size_t)(kv0 + r) * D_DIM + c];
        }
        __syncthreads();

#pragma unroll 8
        for (int k = 0; k < 64; k++) {
            float p[4], vv[4];
#pragma unroll
            for (int i = 0; i < 4; i++) p[i]  = Ps[(ty + 16 * i) * TPAD + k];
#pragma unroll
            for (int j = 0; j < 4; j++) vv[j] = KVs[k * TPAD + (tx + 16 * j)];
#pragma unroll
            for (int i = 0; i < 4; i++)
#pragma unroll
                for (int j = 0; j < 4; j++) o[i][j] += p[i] * vv[j];
        }
        __syncthreads();
    }

#pragma unroll
    for (int i = 0; i < 4; i++) {
        float inv_l = 1.0f / l_i[i];
#pragma unroll
        for (int j = 0; j < 4; j++)
            O[base + (size_t)(q0 + ty + 16 * i) * D_DIM + (tx + 16 * j)] =
                o[i][j] * inv_l;
    }
}

// ===========================================================================
extern "C" void kernel_launch(void* const* d_in, const int* in_sizes, int n_in,
                              void* d_out, int out_size) {
    const float* x  = (const float*)d_in[0];
    const float* wq = (const float*)d_in[1];
    const float* wk = (const float*)d_in[2];
    const float* wv = (const float*)d_in[3];
    const float* wo = (const float*)d_in[4];
    float* out = (float*)d_out;

    float *Qp, *Kp, *Vp, *AOp;
    cudaGetSymbolAddress((void**)&Qp,  g_Q);
    cudaGetSymbolAddress((void**)&Kp,  g_K);
    cudaGetSymbolAddress((void**)&Vp,  g_V);
    cudaGetSymbolAddress((void**)&AOp, g_AO);

    cudaFuncSetAttribute(attn_kernel, cudaFuncAttributeMaxDynamicSharedMemorySize,
                         SMEM_ATTN);

    dim3 ggrid(D_DIM / 128, M_ROWS / 128);   // (8, 64)
    gemm_mma<<<ggrid, 256>>>(x, wq, Qp, M_ROWS, D_DIM, D_DIM);
    gemm_mma<<<ggrid, 256>>>(x, wk, Kp, M_ROWS, D_DIM, D_DIM);
    gemm_mma<<<ggrid, 256>>>(x, wv, Vp, M_ROWS, D_DIM, D_DIM);

    attn_kernel<<<dim3(S_LEN / 64, NB * NH), 256, SMEM_ATTN>>>(Qp, Kp, Vp, AOp);

    gemm_mma<<<ggrid, 256>>>(AOp, wo, out, M_ROWS, D_DIM, D_DIM);
}

// round 4
// speedup vs baseline: 3.8760x; 2.0664x over previous
#include <cuda_runtime.h>
#include <cstdint>

// Problem constants
#define S_LEN 2048
#define D_DIM 1024
#define NB    4
#define NH    16
#define DHD   64
#define M_ROWS (NB * S_LEN)   // 8192

// Scratch (device globals: allocation-free per harness rules)
__device__ float g_Q [M_ROWS * D_DIM];
__device__ float g_K [M_ROWS * D_DIM];
__device__ float g_V [M_ROWS * D_DIM];
__device__ float g_AO[M_ROWS * D_DIM];

// ===========================================================================
// tf32 helpers (legacy mma.sync path — tcgen05 rejected by compute_103 target)
// ===========================================================================
__device__ __forceinline__ uint32_t f2tf32(float f) {
    uint32_t u;
    asm("cvt.rna.tf32.f32 %0, %1;" : "=r"(u) : "f"(f));
    return u;
}

__device__ __forceinline__ void mma_tf32(float c[4], const uint32_t a[4],
                                         const uint32_t b[2]) {
    asm volatile(
        "mma.sync.aligned.m16n8k8.row.col.f32.tf32.tf32.f32 "
        "{%0,%1,%2,%3}, {%4,%5,%6,%7}, {%8,%9}, {%0,%1,%2,%3};"
        : "+f"(c[0]), "+f"(c[1]), "+f"(c[2]), "+f"(c[3])
        : "r"(a[0]), "r"(a[1]), "r"(a[2]), "r"(a[3]), "r"(b[0]), "r"(b[1]));
}

// ===========================================================================
// NT GEMM via tf32 mma.sync (unchanged from R3 — passing at ~250 TF/s)
// ===========================================================================
#define KC     32
#define SSTR   36

__global__ void __launch_bounds__(256) gemm_mma(const float* __restrict__ A,
                                                const float* __restrict__ B,
                                                float* __restrict__ C,
                                                int M, int N, int K) {
    __shared__ float As[128 * SSTR];
    __shared__ float Bs[128 * SSTR];

    const int tid  = threadIdx.x;
    const int lane = tid & 31;
    const int wid  = tid >> 5;
    const int g    = lane >> 2;
    const int t    = lane & 3;
    const int wm   = (wid & 1) * 64;
    const int wn   = (wid >> 1) * 32;

    const int bm = blockIdx.y * 128;
    const int bn = blockIdx.x * 128;

    const int c4  = tid & 7;
    const int lr  = tid >> 3;
    const float* Ag = A + (size_t)(bm + lr) * K + c4 * 4;
    const float* Bg = B + (size_t)(bn + lr) * K + c4 * 4;

    float acc[4][4][4];
#pragma unroll
    for (int i = 0; i < 4; i++)
#pragma unroll
        for (int j = 0; j < 4; j++)
#pragma unroll
            for (int q = 0; q < 4; q++) acc[i][j][q] = 0.0f;

    const int CHUNKS = K / KC;
    float4 pa[4], pb[4];

#pragma unroll
    for (int i = 0; i < 4; i++) {
        pa[i] = *(const float4*)(Ag + (size_t)(i * 32) * K);
        pb[i] = *(const float4*)(Bg + (size_t)(i * 32) * K);
    }

    for (int c = 0; c < CHUNKS; c++) {
#pragma unroll
        for (int i = 0; i < 4; i++) {
            const int row = lr + i * 32;
            uint32_t* as = (uint32_t*)&As[row * SSTR + c4 * 4];
            uint32_t* bs = (uint32_t*)&Bs[row * SSTR + c4 * 4];
            as[0] = f2tf32(pa[i].x); as[1] = f2tf32(pa[i].y);
            as[2] = f2tf32(pa[i].z); as[3] = f2tf32(pa[i].w);
            bs[0] = f2tf32(pb[i].x); bs[1] = f2tf32(pb[i].y);
            bs[2] = f2tf32(pb[i].z); bs[3] = f2tf32(pb[i].w);
        }
        __syncthreads();

        if (c + 1 < CHUNKS) {
            const float* Agn = Ag + (c + 1) * KC;
            const float* Bgn = Bg + (c + 1) * KC;
#pragma unroll
            for (int i = 0; i < 4; i++) {
                pa[i] = *(const float4*)(Agn + (size_t)(i * 32) * K);
                pb[i] = *(const float4*)(Bgn + (size_t)(i * 32) * K);
            }
        }

        const uint32_t* Asu = (const uint32_t*)As;
        const uint32_t* Bsu = (const uint32_t*)Bs;
#pragma unroll
        for (int s = 0; s < 4; s++) {
            const int kb = s * 8;
            uint32_t af[4][4], bf[4][2];
#pragma unroll
            for (int im = 0; im < 4; im++) {
                const int r = wm + im * 16 + g;
                af[im][0] = Asu[r * SSTR + kb + t];
                af[im][1] = Asu[(r + 8) * SSTR + kb + t];
                af[im][2] = Asu[r * SSTR + kb + t + 4];
                af[im][3] = Asu[(r + 8) * SSTR + kb + t + 4];
            }
#pragma unroll
            for (int jn = 0; jn < 4; jn++) {
                const int n = wn + jn * 8 + g;
                bf[jn][0] = Bsu[n * SSTR + kb + t];
                bf[jn][1] = Bsu[n * SSTR + kb + t + 4];
            }
#pragma unroll
            for (int im = 0; im < 4; im++)
#pragma unroll
                for (int jn = 0; jn < 4; jn++)
                    mma_tf32(acc[im][jn], af[im], bf[jn]);
        }
        __syncthreads();
    }

#pragma unroll
    for (int im = 0; im < 4; im++) {
#pragma unroll
        for (int jn = 0; jn < 4; jn++) {
            const int row = bm + wm + im * 16 + g;
            const int col = bn + wn + jn * 8 + 2 * t;
            *(float2*)(C + (size_t)row * N + col) =
                make_float2(acc[im][jn][0], acc[im][jn][1]);
            *(float2*)(C + (size_t)(row + 8) * N + col) =
                make_float2(acc[im][jn][2], acc[im][jn][3]);
        }
    }
}

// ===========================================================================
// Causal flash attention via tf32 mma.sync.
// q-tile 128, kv-tile 64, 256 threads = 8 warps; warp w owns q rows
// [16w,16w+16) x all 64 kv cols -> softmax reductions are quad-local.
// S = Q K^T (mma), online softmax in regs, P -> smem (tf32), O += P V (mma).
// V stored transposed [dh][kv] to act as col-major B operand.
// Smem strides = 68 (== 4 mod 32): conflict-free fragment LDS.
// ===========================================================================
#define QT   128
#define KT   64
#define ASTR 68
#define ATTN_SMEM ((128 * ASTR + 64 * ASTR + 64 * ASTR + 128 * ASTR) * 4)  // 104448

__global__ void __launch_bounds__(256) attn_mma(const float* __restrict__ Q,
                                                const float* __restrict__ K,
                                                const float* __restrict__ V,
                                                float* __restrict__ O) {
    extern __shared__ float smf[];
    float* Qs = smf;                       // [128][68]
    float* Ks = Qs + 128 * ASTR;           // [64][68]
    float* Vs = Ks + 64 * ASTR;            // [64][68]  transposed: [dh][kv]
    float* Ps = Vs + 64 * ASTR;            // [128][68]
    uint32_t* Qu = (uint32_t*)Qs;
    uint32_t* Ku = (uint32_t*)Ks;
    uint32_t* Vu = (uint32_t*)Vs;
    uint32_t* Pu = (uint32_t*)Ps;

    const int bh = blockIdx.y;
    const int b  = bh >> 4;
    const int h  = bh & 15;
    const int q0 = blockIdx.x * QT;

    const int tid  = threadIdx.x;
    const int lane = tid & 31;
    const int wid  = tid >> 5;
    const int g    = lane >> 2;
    const int t    = lane & 3;
    const int row0 = wid * 16;             // warp's q-band within tile

    const size_t base = ((size_t)b * S_LEN) * D_DIM + (size_t)h * DHD;

    // ---- Load Q tile (tf32) ----
    {
        const int c4 = tid & 15, r0 = tid >> 4;
#pragma unroll
        for (int p = 0; p < 8; p++) {
            const int r = r0 + p * 16;
            float4 v = *(const float4*)(Q + base + (size_t)(q0 + r) * D_DIM + c4 * 4);
            uint32_t* d = &Qu[r * ASTR + c4 * 4];
            d[0] = f2tf32(v.x); d[1] = f2tf32(v.y);
            d[2] = f2tf32(v.z); d[3] = f2tf32(v.w);
        }
    }

    float m0 = -1e30f, m1 = -1e30f, l0 = 0.0f, l1 = 0.0f;
    float o[8][4];
#pragma unroll
    for (int n = 0; n < 8; n++)
#pragma unroll
        for (int q = 0; q < 4; q++) o[n][q] = 0.0f;

    const float scale = 0.125f;
    const int qg0 = q0 + row0 + g;     // this thread's first q row
    const int qg1 = qg0 + 8;

    for (int kv0 = 0; kv0 < q0 + QT; kv0 += KT) {
        __syncthreads();   // prior-iter reads of Ks/Vs complete

        // ---- Load K tile (tf32, [kv][dh]) ----
        {
            const int c4 = tid & 15, r0k = tid >> 4;
#pragma unroll
            for (int p = 0; p < 4; p++) {
                const int r = r0k + p * 16;
                float4 v = *(const float4*)(K + base + (size_t)(kv0 + r) * D_DIM + c4 * 4);
                uint32_t* d = &Ku[r * ASTR + c4 * 4];
                d[0] = f2tf32(v.x); d[1] = f2tf32(v.y);
                d[2] = f2tf32(v.z); d[3] = f2tf32(v.w);
            }
        }
        // ---- Load V tile transposed (tf32, [dh][kv]) ----
#pragma unroll
        for (int p = 0; p < 16; p++) {
            const int idx = tid + p * 256;
            const int r = idx >> 6, c = idx & 63;
            Vu[c * ASTR + r] = f2tf32(V[base + (size_t)(kv0 + r) * D_DIM + c]);
        }
        __syncthreads();

        // Warps whose whole band is above this kv tile do no compute
        if (kv0 <= q0 + row0 + 15) {
            // ---- S = Q K^T ----
            float s[8][4];
#pragma unroll
            for (int n = 0; n < 8; n++)
#pragma unroll
                for (int q = 0; q < 4; q++) s[n][q] = 0.0f;

#pragma unroll
            for (int kb = 0; kb < 8; kb++) {
                const int k = kb * 8;
                uint32_t af[4];
                af[0] = Qu[(row0 + g) * ASTR + k + t];
                af[1] = Qu[(row0 + g + 8) * ASTR + k + t];
                af[2] = Qu[(row0 + g) * ASTR + k + t + 4];
                af[3] = Qu[(row0 + g + 8) * ASTR + k + t + 4];
#pragma unroll
                for (int n = 0; n < 8; n++) {
                    uint32_t bf[2];
                    bf[0] = Ku[(n * 8 + g) * ASTR + k + t];
                    bf[1] = Ku[(n * 8 + g) * ASTR + k + t + 4];
                    mma_tf32(s[n], af, bf);
                }
            }

            // ---- Scale + causal mask ----
            const bool need_mask = (kv0 + KT - 1) > (q0 + row0);
            if (need_mask) {
#pragma unroll
                for (int n = 0; n < 8; n++) {
#pragma unroll
                    for (int e = 0; e < 2; e++) {
                        const int kg = kv0 + n * 8 + 2 * t + e;
                        s[n][e]     = (kg <= qg0) ? s[n][e] * scale     : -1e30f;
                        s[n][2 + e] = (kg <= qg1) ? s[n][2 + e] * scale : -1e30f;
                    }
                }
            } else {
#pragma unroll
                for (int n = 0; n < 8; n++)
#pragma unroll
                    for (int q = 0; q < 4; q++) s[n][q] *= scale;
            }

            // ---- Online softmax (rows qg0, qg1; reduce over quad) ----
            float mt0 = -1e30f, mt1 = -1e30f;
#pragma unroll
            for (int n = 0; n < 8; n++) {
                mt0 = fmaxf(mt0, fmaxf(s[n][0], s[n][1]));
                mt1 = fmaxf(mt1, fmaxf(s[n][2], s[n][3]));
            }
            mt0 = fmaxf(mt0, __shfl_xor_sync(0xffffffffu, mt0, 1));
            mt0 = fmaxf(mt0, __shfl_xor_sync(0xffffffffu, mt0, 2));
            mt1 = fmaxf(mt1, __shfl_xor_sync(0xffffffffu, mt1, 1));
            mt1 = fmaxf(mt1, __shfl_xor_sync(0xffffffffu, mt1, 2));

            const float mn0 = fmaxf(m0, mt0);
            const float mn1 = fmaxf(m1, mt1);
            const float cr0 = __expf(m0 - mn0);
            const float cr1 = __expf(m1 - mn1);
            m0 = mn0; m1 = mn1;

            float lt0 = 0.0f, lt1 = 0.0f;
#pragma unroll
            for (int n = 0; n < 8; n++) {
                s[n][0] = __expf(s[n][0] - mn0);
                s[n][1] = __expf(s[n][1] - mn0);
                s[n][2] = __expf(s[n][2] - mn1);
                s[n][3] = __expf(s[n][3] - mn1);
                lt0 += s[n][0] + s[n][1];
                lt1 += s[n][2] + s[n][3];
            }
            lt0 += __shfl_xor_sync(0xffffffffu, lt0, 1);
            lt0 += __shfl_xor_sync(0xffffffffu, lt0, 2);
            lt1 += __shfl_xor_sync(0xffffffffu, lt1, 1);
            lt1 += __shfl_xor_sync(0xffffffffu, lt1, 2);
            l0 = l0 * cr0 + lt0;
            l1 = l1 * cr1 + lt1;

#pragma unroll
            for (int n = 0; n < 8; n++) {
                o[n][0] *= cr0; o[n][1] *= cr0;
                o[n][2] *= cr1; o[n][3] *= cr1;
            }

            // ---- Store P (tf32) to warp-private rows of Ps ----
#pragma unroll
            for (int n = 0; n < 8; n++) {
                uint2 lo = make_uint2(f2tf32(s[n][0]), f2tf32(s[n][1]));
                uint2 hi = make_uint2(f2tf32(s[n][2]), f2tf32(s[n][3]));
                *(uint2*)&Pu[(row0 + g) * ASTR + n * 8 + 2 * t]     = lo;
                *(uint2*)&Pu[(row0 + g + 8) * ASTR + n * 8 + 2 * t] = hi;
            }
            __syncwarp();

            // ---- O += P V ----
#pragma unroll
            for (int kb = 0; kb < 8; kb++) {
                const int k = kb * 8;
                uint32_t af[4];
                af[0] = Pu[(row0 + g) * ASTR + k + t];
                af[1] = Pu[(row0 + g + 8) * ASTR + k + t];
                af[2] = Pu[(row0 + g) * ASTR + k + t + 4];
                af[3] = Pu[(row0 + g + 8) * ASTR + k + t + 4];
#pragma unroll
                for (int n = 0; n < 8; n++) {
                    uint32_t bf[2];
                    bf[0] = Vu[(n * 8 + g) * ASTR + k + t];
                    bf[1] = Vu[(n * 8 + g) * ASTR + k + t + 4];
                    mma_tf32(o[n], af, bf);
                }
            }
        }
    }

    // ---- Normalize + write (layout [b*S+s][h*64+dh]) ----
    const float inv0 = 1.0f / l0;
    const float inv1 = 1.0f / l1;
#pragma unroll
    for (int n = 0; n < 8; n++) {
        const int col = n * 8 + 2 * t;
        *(float2*)(O + base + (size_t)qg0 * D_DIM + col) =
            make_float2(o[n][0] * inv0, o[n][1] * inv0);
        *(float2*)(O + base + (size_t)qg1 * D_DIM + col) =
            make_float2(o[n][2] * inv1, o[n][3] * inv1);
    }
}

// ===========================================================================
extern "C" void kernel_launch(void* const* d_in, const int* in_sizes, int n_in,
                              void* d_out, int out_size) {
    const float* x  = (const float*)d_in[0];
    const float* wq = (const float*)d_in[1];
    const float* wk = (const float*)d_in[2];
    const float* wv = (const float*)d_in[3];
    const float* wo = (const float*)d_in[4];
    float* out = (float*)d_out;

    float *Qp, *Kp, *Vp, *AOp;
    cudaGetSymbolAddress((void**)&Qp,  g_Q);
    cudaGetSymbolAddress((void**)&Kp,  g_K);
    cudaGetSymbolAddress((void**)&Vp,  g_V);
    cudaGetSymbolAddress((void**)&AOp, g_AO);

    cudaFuncSetAttribute(attn_mma, cudaFuncAttributeMaxDynamicSharedMemorySize,
                         ATTN_SMEM);

    dim3 ggrid(D_DIM / 128, M_ROWS / 128);   // (8, 64)
    gemm_mma<<<ggrid, 256>>>(x, wq, Qp, M_ROWS, D_DIM, D_DIM);
    gemm_mma<<<ggrid, 256>>>(x, wk, Kp, M_ROWS, D_DIM, D_DIM);
    gemm_mma<<<ggrid, 256>>>(x, wv, Vp, M_ROWS, D_DIM, D_DIM);

    attn_mma<<<dim3(S_LEN / QT, NB * NH), 256, ATTN_SMEM>>>(Qp, Kp, Vp, AOp);

    gemm_mma<<<ggrid, 256>>>(AOp, wo, out, M_ROWS, D_DIM, D_DIM);
}

// round 5
// speedup vs baseline: 5.4003x; 1.3933x over previous
#include <cuda_runtime.h>
#include <cuda_fp16.h>
#include <cstdint>

// Problem constants
#define S_LEN 2048
#define D_DIM 1024
#define NB    4
#define NH    16
#define DHD   64
#define M_ROWS (NB * S_LEN)   // 8192

// Scratch (device globals: allocation-free per harness rules)
__device__ float g_Q [M_ROWS * D_DIM];
__device__ float g_K [M_ROWS * D_DIM];
__device__ float g_V [M_ROWS * D_DIM];
__device__ float g_AO[M_ROWS * D_DIM];

// ===========================================================================
// fp16 helpers (legacy mma.sync path — tcgen05 rejected by compute_103 target)
// fp16 mantissa (10 bits) == tf32 mantissa, so no accuracy loss vs tf32,
// but m16n8k16 gives 2x K per MMA and half the operand bytes.
// ===========================================================================
__device__ __forceinline__ uint32_t f2h2(float lo, float hi) {
    uint32_t u;
    asm("cvt.rn.f16x2.f32 %0, %1, %2;" : "=r"(u) : "f"(hi), "f"(lo));
    return u;   // lower 16 bits = lo (even index), upper = hi
}

__device__ __forceinline__ void mma_f16(float c[4], const uint32_t a[4],
                                        const uint32_t b[2]) {
    asm volatile(
        "mma.sync.aligned.m16n8k16.row.col.f32.f16.f16.f32 "
        "{%0,%1,%2,%3}, {%4,%5,%6,%7}, {%8,%9}, {%0,%1,%2,%3};"
        : "+f"(c[0]), "+f"(c[1]), "+f"(c[2]), "+f"(c[3])
        : "r"(a[0]), "r"(a[1]), "r"(a[2]), "r"(a[3]), "r"(b[0]), "r"(b[1]));
}

// ===========================================================================
// NT GEMM via fp16 mma.sync: C[m,n] = sum_k A[m,k] * B[n,k]
// 128x128 CTA tile, 256 threads (8 warps, 2Mx4N), warp tile 64x32.
// K chunk = 32 (2 x k16 steps), register-prefetch double buffering.
// smem rows: 40 halves (20 words; 20 mod 8 == 4 -> fragment LDS conflict-free)
// ===========================================================================
#define KC     32
#define GSTRH  40            // halves per row
#define GSTRW  20            // words per row

__global__ void __launch_bounds__(256) gemm_mma(const float* __restrict__ A,
                                                const float* __restrict__ B,
                                                float* __restrict__ C,
                                                int M, int N, int K) {
    __shared__ __half As[128 * GSTRH];
    __shared__ __half Bs[128 * GSTRH];
    uint32_t* Asu = (uint32_t*)As;
    uint32_t* Bsu = (uint32_t*)Bs;

    const int tid  = threadIdx.x;
    const int lane = tid & 31;
    const int wid  = tid >> 5;
    const int g    = lane >> 2;
    const int t    = lane & 3;
    const int wm   = (wid & 1) * 64;
    const int wn   = (wid >> 1) * 32;

    const int bm = blockIdx.y * 128;
    const int bn = blockIdx.x * 128;

    const int c4  = tid & 7;      // float4 slot within 32-float chunk row
    const int lr  = tid >> 3;     // base row 0..31
    const float* Ag = A + (size_t)(bm + lr) * K + c4 * 4;
    const float* Bg = B + (size_t)(bn + lr) * K + c4 * 4;

    float acc[4][4][4];
#pragma unroll
    for (int i = 0; i < 4; i++)
#pragma unroll
        for (int j = 0; j < 4; j++)
#pragma unroll
            for (int q = 0; q < 4; q++) acc[i][j][q] = 0.0f;

    const int CHUNKS = K / KC;
    float4 pa[4], pb[4];

#pragma unroll
    for (int i = 0; i < 4; i++) {
        pa[i] = *(const float4*)(Ag + (size_t)(i * 32) * K);
        pb[i] = *(const float4*)(Bg + (size_t)(i * 32) * K);
    }

    for (int c = 0; c < CHUNKS; c++) {
        // Store prefetched chunk to smem as fp16 (uint2 = 4 halves)
#pragma unroll
        for (int i = 0; i < 4; i++) {
            const int row = lr + i * 32;
            uint2 ha = make_uint2(f2h2(pa[i].x, pa[i].y), f2h2(pa[i].z, pa[i].w));
            uint2 hb = make_uint2(f2h2(pb[i].x, pb[i].y), f2h2(pb[i].z, pb[i].w));
            *(uint2*)&Asu[row * GSTRW + c4 * 2] = ha;
            *(uint2*)&Bsu[row * GSTRW + c4 * 2] = hb;
        }
        __syncthreads();

        if (c + 1 < CHUNKS) {
            const float* Agn = Ag + (c + 1) * KC;
            const float* Bgn = Bg + (c + 1) * KC;
#pragma unroll
            for (int i = 0; i < 4; i++) {
                pa[i] = *(const float4*)(Agn + (size_t)(i * 32) * K);
                pb[i] = *(const float4*)(Bgn + (size_t)(i * 32) * K);
            }
        }

        // 2 x k16 steps cover the 32-wide chunk
#pragma unroll
        for (int s = 0; s < 2; s++) {
            const int kw = s * 8;    // word offset (16 halves)
            uint32_t af[4][4], bf[4][2];
#pragma unroll
            for (int im = 0; im < 4; im++) {
                const int r = wm + im * 16 + g;
                af[im][0] = Asu[r * GSTRW + kw + t];
                af[im][1] = Asu[(r + 8) * GSTRW + kw + t];
                af[im][2] = Asu[r * GSTRW + kw + t + 4];
                af[im][3] = Asu[(r + 8) * GSTRW + kw + t + 4];
            }
#pragma unroll
            for (int jn = 0; jn < 4; jn++) {
                const int n = wn + jn * 8 + g;
                bf[jn][0] = Bsu[n * GSTRW + kw + t];
                bf[jn][1] = Bsu[n * GSTRW + kw + t + 4];
            }
#pragma unroll
            for (int im = 0; im < 4; im++)
#pragma unroll
                for (int jn = 0; jn < 4; jn++)
                    mma_f16(acc[im][jn], af[im], bf[jn]);
        }
        __syncthreads();
    }

#pragma unroll
    for (int im = 0; im < 4; im++) {
#pragma unroll
        for (int jn = 0; jn < 4; jn++) {
            const int row = bm + wm + im * 16 + g;
            const int col = bn + wn + jn * 8 + 2 * t;
            *(float2*)(C + (size_t)row * N + col) =
                make_float2(acc[im][jn][0], acc[im][jn][1]);
            *(float2*)(C + (size_t)(row + 8) * N + col) =
                make_float2(acc[im][jn][2], acc[im][jn][3]);
        }
    }
}

// ===========================================================================
// Causal flash attention via fp16 mma.sync (m16n8k16, f32 accumulate).
// q-tile 128, kv-tile 64, 8 warps; warp w owns q rows [16w,16w+16).
// Smem rows: 72 halves (36 words; 36 mod 8 == 4 -> conflict-free fragments).
// V stored transposed [dh][kv] as the col-major B operand of O += P V.
// ===========================================================================
#define QT    128
#define KT    64
#define AST   72                       // halves per row
#define ASTW  36                       // words per row
// halves: Q 128*72, K 64*72, V 64*72, P 128*72  -> 27648 halves = 55296 B
#define ATTN_SMEM (27648 * 2)

__global__ void __launch_bounds__(256) attn_mma(const float* __restrict__ Q,
                                                const float* __restrict__ K,
                                                const float* __restrict__ V,
                                                float* __restrict__ O) {
    extern __shared__ __half smh[];
    __half* Qs = smh;                   // [128][72]
    __half* Ks = Qs + 128 * AST;        // [64][72]
    __half* Vs = Ks + 64 * AST;         // [64][72] transposed: [dh][kv]
    __half* Ps = Vs + 64 * AST;         // [128][72]
    uint32_t* Qu = (uint32_t*)Qs;
    uint32_t* Ku = (uint32_t*)Ks;
    uint32_t* Vu = (uint32_t*)Vs;
    uint32_t* Pu = (uint32_t*)Ps;

    const int bh = blockIdx.y;
    const int b  = bh >> 4;
    const int h  = bh & 15;
    const int q0 = blockIdx.x * QT;

    const int tid  = threadIdx.x;
    const int lane = tid & 31;
    const int wid  = tid >> 5;
    const int g    = lane >> 2;
    const int t    = lane & 3;
    const int row0 = wid * 16;

    const size_t base = ((size_t)b * S_LEN) * D_DIM + (size_t)h * DHD;

    // ---- Load Q tile (fp16) ----
    {
        const int c4 = tid & 15, r0 = tid >> 4;
#pragma unroll
        for (int p = 0; p < 8; p++) {
            const int r = r0 + p * 16;
            float4 v = *(const float4*)(Q + base + (size_t)(q0 + r) * D_DIM + c4 * 4);
            *(uint2*)&Qu[r * ASTW + c4 * 2] =
                make_uint2(f2h2(v.x, v.y), f2h2(v.z, v.w));
        }
    }

    float m0 = -1e30f, m1 = -1e30f, l0 = 0.0f, l1 = 0.0f;
    float o[8][4];
#pragma unroll
    for (int n = 0; n < 8; n++)
#pragma unroll
        for (int q = 0; q < 4; q++) o[n][q] = 0.0f;

    const float scale = 0.125f;
    const int qg0 = q0 + row0 + g;
    const int qg1 = qg0 + 8;

    for (int kv0 = 0; kv0 < q0 + QT; kv0 += KT) {
        __syncthreads();

        // ---- Load K tile (fp16, [kv][dh]) ----
        {
            const int c4 = tid & 15, r0k = tid >> 4;
#pragma unroll
            for (int p = 0; p < 4; p++) {
                const int r = r0k + p * 16;
                float4 v = *(const float4*)(K + base + (size_t)(kv0 + r) * D_DIM + c4 * 4);
                *(uint2*)&Ku[r * ASTW + c4 * 2] =
                    make_uint2(f2h2(v.x, v.y), f2h2(v.z, v.w));
            }
        }
        // ---- Load V tile transposed (fp16, [dh][kv]) ----
#pragma unroll
        for (int p = 0; p < 16; p++) {
            const int idx = tid + p * 256;
            const int r = idx >> 6, c = idx & 63;
            Vs[c * AST + r] = __float2half_rn(V[base + (size_t)(kv0 + r) * D_DIM + c]);
        }
        __syncthreads();

        if (kv0 <= q0 + row0 + 15) {
            // ---- S = Q K^T (4 x k16 steps) ----
            float s[8][4];
#pragma unroll
            for (int n = 0; n < 8; n++)
#pragma unroll
                for (int q = 0; q < 4; q++) s[n][q] = 0.0f;

#pragma unroll
            for (int kb = 0; kb < 4; kb++) {
                const int kw = kb * 8;
                uint32_t af[4];
                af[0] = Qu[(row0 + g) * ASTW + kw + t];
                af[1] = Qu[(row0 + g + 8) * ASTW + kw + t];
                af[2] = Qu[(row0 + g) * ASTW + kw + t + 4];
                af[3] = Qu[(row0 + g + 8) * ASTW + kw + t + 4];
#pragma unroll
                for (int n = 0; n < 8; n++) {
                    uint32_t bf[2];
                    bf[0] = Ku[(n * 8 + g) * ASTW + kw + t];
                    bf[1] = Ku[(n * 8 + g) * ASTW + kw + t + 4];
                    mma_f16(s[n], af, bf);
                }
            }

            // ---- Scale + causal mask ----
            const bool need_mask = (kv0 + KT - 1) > (q0 + row0);
            if (need_mask) {
#pragma unroll
                for (int n = 0; n < 8; n++) {
#pragma unroll
                    for (int e = 0; e < 2; e++) {
                        const int kg = kv0 + n * 8 + 2 * t + e;
                        s[n][e]     = (kg <= qg0) ? s[n][e] * scale     : -1e30f;
                        s[n][2 + e] = (kg <= qg1) ? s[n][2 + e] * scale : -1e30f;
                    }
                }
            } else {
#pragma unroll
                for (int n = 0; n < 8; n++)
#pragma unroll
                    for (int q = 0; q < 4; q++) s[n][q] *= scale;
            }

            // ---- Online softmax (quad-local reductions) ----
            float mt0 = -1e30f, mt1 = -1e30f;
#pragma unroll
            for (int n = 0; n < 8; n++) {
                mt0 = fmaxf(mt0, fmaxf(s[n][0], s[n][1]));
                mt1 = fmaxf(mt1, fmaxf(s[n][2], s[n][3]));
            }
            mt0 = fmaxf(mt0, __shfl_xor_sync(0xffffffffu, mt0, 1));
            mt0 = fmaxf(mt0, __shfl_xor_sync(0xffffffffu, mt0, 2));
            mt1 = fmaxf(mt1, __shfl_xor_sync(0xffffffffu, mt1, 1));
            mt1 = fmaxf(mt1, __shfl_xor_sync(0xffffffffu, mt1, 2));

            const float mn0 = fmaxf(m0, mt0);
            const float mn1 = fmaxf(m1, mt1);
            const float cr0 = __expf(m0 - mn0);
            const float cr1 = __expf(m1 - mn1);
            m0 = mn0; m1 = mn1;

            float lt0 = 0.0f, lt1 = 0.0f;
#pragma unroll
            for (int n = 0; n < 8; n++) {
                s[n][0] = __expf(s[n][0] - mn0);
                s[n][1] = __expf(s[n][1] - mn0);
                s[n][2] = __expf(s[n][2] - mn1);
                s[n][3] = __expf(s[n][3] - mn1);
                lt0 += s[n][0] + s[n][1];
                lt1 += s[n][2] + s[n][3];
            }
            lt0 += __shfl_xor_sync(0xffffffffu, lt0, 1);
            lt0 += __shfl_xor_sync(0xffffffffu, lt0, 2);
            lt1 += __shfl_xor_sync(0xffffffffu, lt1, 1);
            lt1 += __shfl_xor_sync(0xffffffffu, lt1, 2);
            l0 = l0 * cr0 + lt0;
            l1 = l1 * cr1 + lt1;

#pragma unroll
            for (int n = 0; n < 8; n++) {
                o[n][0] *= cr0; o[n][1] *= cr0;
                o[n][2] *= cr1; o[n][3] *= cr1;
            }

            // ---- Store P (fp16) to warp-private rows of Ps ----
#pragma unroll
            for (int n = 0; n < 8; n++) {
                Pu[(row0 + g) * ASTW + n * 4 + t]     = f2h2(s[n][0], s[n][1]);
                Pu[(row0 + g + 8) * ASTW + n * 4 + t] = f2h2(s[n][2], s[n][3]);
            }
            __syncwarp();

            // ---- O += P V (4 x k16 steps over kv) ----
#pragma unroll
            for (int kb = 0; kb < 4; kb++) {
                const int kw = kb * 8;
                uint32_t af[4];
                af[0] = Pu[(row0 + g) * ASTW + kw + t];
                af[1] = Pu[(row0 + g + 8) * ASTW + kw + t];
                af[2] = Pu[(row0 + g) * ASTW + kw + t + 4];
                af[3] = Pu[(row0 + g + 8) * ASTW + kw + t + 4];
#pragma unroll
                for (int n = 0; n < 8; n++) {
                    uint32_t bf[2];
                    bf[0] = Vu[(n * 8 + g) * ASTW + kw + t];
                    bf[1] = Vu[(n * 8 + g) * ASTW + kw + t + 4];
                    mma_f16(o[n], af, bf);
                }
            }
        }
    }

    // ---- Normalize + write (layout [b*S+s][h*64+dh]) ----
    const float inv0 = 1.0f / l0;
    const float inv1 = 1.0f / l1;
#pragma unroll
    for (int n = 0; n < 8; n++) {
        const int col = n * 8 + 2 * t;
        *(float2*)(O + base + (size_t)qg0 * D_DIM + col) =
            make_float2(o[n][0] * inv0, o[n][1] * inv0);
        *(float2*)(O + base + (size_t)qg1 * D_DIM + col) =
            make_float2(o[n][2] * inv1, o[n][3] * inv1);
    }
}

// ===========================================================================
extern "C" void kernel_launch(void* const* d_in, const int* in_sizes, int n_in,
                              void* d_out, int out_size) {
    const float* x  = (const float*)d_in[0];
    const float* wq = (const float*)d_in[1];
    const float* wk = (const float*)d_in[2];
    const float* wv = (const float*)d_in[3];
    const float* wo = (const float*)d_in[4];
    float* out = (float*)d_out;

    float *Qp, *Kp, *Vp, *AOp;
    cudaGetSymbolAddress((void**)&Qp,  g_Q);
    cudaGetSymbolAddress((void**)&Kp,  g_K);
    cudaGetSymbolAddress((void**)&Vp,  g_V);
    cudaGetSymbolAddress((void**)&AOp, g_AO);

    cudaFuncSetAttribute(attn_mma, cudaFuncAttributeMaxDynamicSharedMemorySize,
                         ATTN_SMEM);

    dim3 ggrid(D_DIM / 128, M_ROWS / 128);   // (8, 64)
    gemm_mma<<<ggrid, 256>>>(x, wq, Qp, M_ROWS, D_DIM, D_DIM);
    gemm_mma<<<ggrid, 256>>>(x, wk, Kp, M_ROWS, D_DIM, D_DIM);
    gemm_mma<<<ggrid, 256>>>(x, wv, Vp, M_ROWS, D_DIM, D_DIM);

    attn_mma<<<dim3(S_LEN / QT, NB * NH), 256, ATTN_SMEM>>>(Qp, Kp, Vp, AOp);

    gemm_mma<<<ggrid, 256>>>(AOp, wo, out, M_ROWS, D_DIM, D_DIM);
}

// round 6
// speedup vs baseline: 8.5973x; 1.5920x over previous
#include <cuda_runtime.h>
#include <cuda_fp16.h>
#include <cstdint>

// Problem constants
#define S_LEN 2048
#define D_DIM 1024
#define NB    4
#define NH    16
#define DHD   64
#define M_ROWS (NB * S_LEN)   // 8192

// Scratch (device globals: allocation-free per harness rules)
__device__ float  g_Q  [M_ROWS * D_DIM];
__device__ float  g_K  [M_ROWS * D_DIM];
__device__ float  g_V  [M_ROWS * D_DIM];
__device__ float  g_AO [M_ROWS * D_DIM];
__device__ __half g_xh [M_ROWS * D_DIM];
__device__ __half g_wqh[D_DIM * D_DIM];
__device__ __half g_wkh[D_DIM * D_DIM];
__device__ __half g_wvh[D_DIM * D_DIM];
__device__ __half g_woh[D_DIM * D_DIM];
__device__ __half g_aoh[M_ROWS * D_DIM];

// ===========================================================================
// Helpers
// ===========================================================================
__device__ __forceinline__ uint32_t f2h2(float lo, float hi) {
    uint32_t u;
    asm("cvt.rn.f16x2.f32 %0, %1, %2;" : "=r"(u) : "f"(hi), "f"(lo));
    return u;   // low 16 bits = lo
}

__device__ __forceinline__ void mma_f16(float c[4], const uint32_t a[4],
                                        const uint32_t b[2]) {
    asm volatile(
        "mma.sync.aligned.m16n8k16.row.col.f32.f16.f16.f32 "
        "{%0,%1,%2,%3}, {%4,%5,%6,%7}, {%8,%9}, {%0,%1,%2,%3};"
        : "+f"(c[0]), "+f"(c[1]), "+f"(c[2]), "+f"(c[3])
        : "r"(a[0]), "r"(a[1]), "r"(a[2]), "r"(a[3]), "r"(b[0]), "r"(b[1]));
}

__device__ __forceinline__ void ldm_x4(uint32_t& r0, uint32_t& r1,
                                       uint32_t& r2, uint32_t& r3,
                                       uint32_t addr) {
    asm volatile("ldmatrix.sync.aligned.m8n8.x4.shared.b16 {%0,%1,%2,%3}, [%4];"
                 : "=r"(r0), "=r"(r1), "=r"(r2), "=r"(r3) : "r"(addr));
}
__device__ __forceinline__ void ldm_x4_t(uint32_t& r0, uint32_t& r1,
                                         uint32_t& r2, uint32_t& r3,
                                         uint32_t addr) {
    asm volatile("ldmatrix.sync.aligned.m8n8.x4.trans.shared.b16 {%0,%1,%2,%3}, [%4];"
                 : "=r"(r0), "=r"(r1), "=r"(r2), "=r"(r3) : "r"(addr));
}

// ===========================================================================
// fp32 -> fp16 convert (vectorized)
// ===========================================================================
__global__ void __launch_bounds__(256) f2h_kernel(const float* __restrict__ src,
                                                  __half* __restrict__ dst,
                                                  int n4) {
    int i = blockIdx.x * 256 + threadIdx.x;
    if (i < n4) {
        float4 v = ((const float4*)src)[i];
        ((uint2*)dst)[i] = make_uint2(f2h2(v.x, v.y), f2h2(v.z, v.w));
    }
}

// ===========================================================================
// fp16 NT GEMM: C[m,n] = sum_k A[m,k]*B[n,k], fp32 out.
// 128x128 tile, 256 threads (8 warps 2Mx4N, warp 64x32), KC=64,
// 3-stage cp.async pipeline, ldmatrix fragments.
// smem rows: 72 halves (144B): ldmatrix rows land on disjoint bank groups.
// ===========================================================================
#define GKC        64
#define GSTR       72
#define GSTAGES    3
#define GTILE_H    (128 * GSTR)             // halves per matrix per stage
#define GSTAGE_H   (2 * GTILE_H)
#define GEMM_SMEM  (GSTAGES * GSTAGE_H * 2) // 110592 bytes

__global__ void __launch_bounds__(256) gemm_h(const __half* __restrict__ A,
                                              const __half* __restrict__ B,
                                              float* __restrict__ C,
                                              int M, int N, int K) {
    extern __shared__ __half sh[];
    const uint32_t sbase = (uint32_t)__cvta_generic_to_shared(sh);

    const int tid  = threadIdx.x;
    const int lane = tid & 31;
    const int wid  = tid >> 5;
    const int g    = lane >> 2;
    const int t    = lane & 3;
    const int wm   = (wid & 1) * 64;
    const int wn   = (wid >> 1) * 32;
    const int bm   = blockIdx.y * 128;
    const int bn   = blockIdx.x * 128;

    const int arow = (lane & 7) + ((lane & 8) ? 8 : 0);
    const int acol = (lane & 16) ? 8 : 0;
    const int brow = (lane & 7) + ((lane & 16) ? 8 : 0);
    const int bcol = (lane & 8) ? 8 : 0;

    float acc[4][4][4];
#pragma unroll
    for (int i = 0; i < 4; i++)
#pragma unroll
        for (int j = 0; j < 4; j++)
#pragma unroll
            for (int q = 0; q < 4; q++) acc[i][j][q] = 0.0f;

    const int CHUNKS = K / GKC;   // 16

    // ---- cp.async issue of one 128x64 A tile + B tile ----
    auto issue = [&](int chunk, int st) {
        const __half* Agc = A + (size_t)bm * K + chunk * GKC;
        const __half* Bgc = B + (size_t)bn * K + chunk * GKC;
        const uint32_t sA = sbase + (uint32_t)(st * GSTAGE_H) * 2;
        const uint32_t sB = sA + (uint32_t)GTILE_H * 2;
#pragma unroll
        for (int i = 0; i < 4; i++) {
            const int cid = tid + i * 256;
            const int row = cid >> 3, c16 = cid & 7;
            const __half* ga = Agc + (size_t)row * K + c16 * 8;
            const __half* gb = Bgc + (size_t)row * K + c16 * 8;
            const uint32_t da = sA + (uint32_t)(row * GSTR + c16 * 8) * 2;
            const uint32_t db = sB + (uint32_t)(row * GSTR + c16 * 8) * 2;
            asm volatile("cp.async.cg.shared.global [%0], [%1], 16;" :: "r"(da), "l"(ga));
            asm volatile("cp.async.cg.shared.global [%0], [%1], 16;" :: "r"(db), "l"(gb));
        }
    };

    // Prologue: stages 0..GSTAGES-2
#pragma unroll
    for (int s = 0; s < GSTAGES - 1; s++) {
        issue(s, s);
        asm volatile("cp.async.commit_group;");
    }

    for (int c = 0; c < CHUNKS; c++) {
        const int nc = c + GSTAGES - 1;
        if (nc < CHUNKS) issue(nc, nc % GSTAGES);
        asm volatile("cp.async.commit_group;");
        asm volatile("cp.async.wait_group 2;");
        __syncthreads();

        const int st = c % GSTAGES;
        const uint32_t aBase = sbase + (uint32_t)(st * GSTAGE_H) * 2;
        const uint32_t bBase = aBase + (uint32_t)GTILE_H * 2;

#pragma unroll
        for (int kb = 0; kb < 4; kb++) {
            uint32_t af[4][4], bf[4][2];
#pragma unroll
            for (int im = 0; im < 4; im++) {
                const uint32_t addr =
                    aBase + (uint32_t)((wm + im * 16 + arow) * GSTR + kb * 16 + acol) * 2;
                ldm_x4(af[im][0], af[im][1], af[im][2], af[im][3], addr);
            }
#pragma unroll
            for (int p = 0; p < 2; p++) {
                uint32_t r0, r1, r2, r3;
                const uint32_t addr =
                    bBase + (uint32_t)((wn + p * 16 + brow) * GSTR + kb * 16 + bcol) * 2;
                ldm_x4(r0, r1, r2, r3, addr);
                bf[2 * p][0] = r0; bf[2 * p][1] = r1;
                bf[2 * p + 1][0] = r2; bf[2 * p + 1][1] = r3;
            }
#pragma unroll
            for (int im = 0; im < 4; im++)
#pragma unroll
                for (int jn = 0; jn < 4; jn++)
                    mma_f16(acc[im][jn], af[im], bf[jn]);
        }
        __syncthreads();
    }

#pragma unroll
    for (int im = 0; im < 4; im++) {
#pragma unroll
        for (int jn = 0; jn < 4; jn++) {
            const int row = bm + wm + im * 16 + g;
            const int col = bn + wn + jn * 8 + 2 * t;
            *(float2*)(C + (size_t)row * N + col) =
                make_float2(acc[im][jn][0], acc[im][jn][1]);
            *(float2*)(C + (size_t)(row + 8) * N + col) =
                make_float2(acc[im][jn][2], acc[im][jn][3]);
        }
    }
}

// ===========================================================================
// Causal flash attention, fp16 mma.sync:
//  - Q fragments hoisted into registers (loaded once via ldmatrix)
//  - P accumulator -> A-fragment directly in registers (no smem round-trip)
//  - K via ldmatrix, V stored [kv][dh] and read via ldmatrix.trans
// ===========================================================================
#define QT   128
#define KT   64
#define AST  72     // halves per smem row
#define ASTW 36     // words per smem row

__global__ void __launch_bounds__(256, 2) attn_mma(const float* __restrict__ Q,
                                                   const float* __restrict__ K,
                                                   const float* __restrict__ V,
                                                   float* __restrict__ O) {
    __shared__ __half Qs[128 * AST];
    __shared__ __half Ks[64 * AST];
    __shared__ __half Vs[64 * AST];
    uint32_t* Qu = (uint32_t*)Qs;
    uint32_t* Ku = (uint32_t*)Ks;
    uint32_t* Vu = (uint32_t*)Vs;
    const uint32_t qbase = (uint32_t)__cvta_generic_to_shared(Qs);
    const uint32_t kbase = (uint32_t)__cvta_generic_to_shared(Ks);
    const uint32_t vbase = (uint32_t)__cvta_generic_to_shared(Vs);

    const int bh = blockIdx.y;
    const int b  = bh >> 4;
    const int h  = bh & 15;
    const int q0 = blockIdx.x * QT;

    const int tid  = threadIdx.x;
    const int lane = tid & 31;
    const int wid  = tid >> 5;
    const int g    = lane >> 2;
    const int t    = lane & 3;
    const int row0 = wid * 16;

    const int arow = (lane & 7) + ((lane & 8) ? 8 : 0);   // A/V-trans row piece
    const int acol = (lane & 16) ? 8 : 0;
    const int brow = (lane & 7) + ((lane & 16) ? 8 : 0);  // B row piece
    const int bcol = (lane & 8) ? 8 : 0;

    const size_t base = ((size_t)b * S_LEN) * D_DIM + (size_t)h * DHD;

    // ---- Load Q tile (fp32 -> fp16 smem) ----
    {
        const int c4 = tid & 15, r0q = tid >> 4;
#pragma unroll
        for (int p = 0; p < 8; p++) {
            const int r = r0q + p * 16;
            float4 v = *(const float4*)(Q + base + (size_t)(q0 + r) * D_DIM + c4 * 4);
            *(uint2*)&Qu[r * ASTW + c4 * 2] =
                make_uint2(f2h2(v.x, v.y), f2h2(v.z, v.w));
        }
    }
    __syncthreads();

    // ---- Hoist Q fragments (warp's 16-row band; reused for all kv tiles) ----
    uint32_t qf[4][4];
#pragma unroll
    for (int kb = 0; kb < 4; kb++) {
        const uint32_t addr =
            qbase + (uint32_t)((row0 + arow) * AST + kb * 16 + acol) * 2;
        ldm_x4(qf[kb][0], qf[kb][1], qf[kb][2], qf[kb][3], addr);
    }

    float m0 = -1e30f, m1 = -1e30f, l0 = 0.0f, l1 = 0.0f;
    float o[8][4];
#pragma unroll
    for (int n = 0; n < 8; n++)
#pragma unroll
        for (int q = 0; q < 4; q++) o[n][q] = 0.0f;

    const float scale = 0.125f;
    const int qg0 = q0 + row0 + g;
    const int qg1 = qg0 + 8;

    for (int kv0 = 0; kv0 < q0 + QT; kv0 += KT) {
        __syncthreads();   // prior-iter fragment reads of Ks/Vs complete

        // ---- Load K and V tiles (fp32 -> fp16, natural [kv][dh]) ----
        {
            const int c4 = tid & 15, r0k = tid >> 4;
#pragma unroll
            for (int p = 0; p < 4; p++) {
                const int r = r0k + p * 16;
                float4 vk = *(const float4*)(K + base + (size_t)(kv0 + r) * D_DIM + c4 * 4);
                float4 vv = *(const float4*)(V + base + (size_t)(kv0 + r) * D_DIM + c4 * 4);
                *(uint2*)&Ku[r * ASTW + c4 * 2] =
                    make_uint2(f2h2(vk.x, vk.y), f2h2(vk.z, vk.w));
                *(uint2*)&Vu[r * ASTW + c4 * 2] =
                    make_uint2(f2h2(vv.x, vv.y), f2h2(vv.z, vv.w));
            }
        }
        __syncthreads();

        if (kv0 <= q0 + row0 + 15) {
            // ---- S = Q K^T ----
            float s[8][4];
#pragma unroll
            for (int n = 0; n < 8; n++)
#pragma unroll
                for (int q = 0; q < 4; q++) s[n][q] = 0.0f;

#pragma unroll
            for (int kb = 0; kb < 4; kb++) {
#pragma unroll
                for (int p = 0; p < 4; p++) {      // kv n-block pairs
                    uint32_t r0, r1, r2, r3;
                    const uint32_t addr =
                        kbase + (uint32_t)((p * 16 + brow) * AST + kb * 16 + bcol) * 2;
                    ldm_x4(r0, r1, r2, r3, addr);
                    uint32_t bf0[2] = {r0, r1};
                    uint32_t bf1[2] = {r2, r3};
                    mma_f16(s[2 * p],     qf[kb], bf0);
                    mma_f16(s[2 * p + 1], qf[kb], bf1);
                }
            }

            // ---- Scale + causal mask ----
            const bool need_mask = (kv0 + KT - 1) > (q0 + row0);
            if (need_mask) {
#pragma unroll
                for (int n = 0; n < 8; n++) {
#pragma unroll
                    for (int e = 0; e < 2; e++) {
                        const int kg = kv0 + n * 8 + 2 * t + e;
                        s[n][e]     = (kg <= qg0) ? s[n][e] * scale     : -1e30f;
                        s[n][2 + e] = (kg <= qg1) ? s[n][2 + e] * scale : -1e30f;
                    }
                }
            } else {
#pragma unroll
                for (int n = 0; n < 8; n++)
#pragma unroll
                    for (int q = 0; q < 4; q++) s[n][q] *= scale;
            }

            // ---- Online softmax (quad-local reductions) ----
            float mt0 = -1e30f, mt1 = -1e30f;
#pragma unroll
            for (int n = 0; n < 8; n++) {
                mt0 = fmaxf(mt0, fmaxf(s[n][0], s[n][1]));
                mt1 = fmaxf(mt1, fmaxf(s[n][2], s[n][3]));
            }
            mt0 = fmaxf(mt0, __shfl_xor_sync(0xffffffffu, mt0, 1));
            mt0 = fmaxf(mt0, __shfl_xor_sync(0xffffffffu, mt0, 2));
            mt1 = fmaxf(mt1, __shfl_xor_sync(0xffffffffu, mt1, 1));
            mt1 = fmaxf(mt1, __shfl_xor_sync(0xffffffffu, mt1, 2));

            const float mn0 = fmaxf(m0, mt0);
            const float mn1 = fmaxf(m1, mt1);
            const float cr0 = __expf(m0 - mn0);
            const float cr1 = __expf(m1 - mn1);
            m0 = mn0; m1 = mn1;

            float lt0 = 0.0f, lt1 = 0.0f;
#pragma unroll
            for (int n = 0; n < 8; n++) {
                s[n][0] = __expf(s[n][0] - mn0);
                s[n][1] = __expf(s[n][1] - mn0);
                s[n][2] = __expf(s[n][2] - mn1);
                s[n][3] = __expf(s[n][3] - mn1);
                lt0 += s[n][0] + s[n][1];
                lt1 += s[n][2] + s[n][3];
            }
            lt0 += __shfl_xor_sync(0xffffffffu, lt0, 1);
            lt0 += __shfl_xor_sync(0xffffffffu, lt0, 2);
            lt1 += __shfl_xor_sync(0xffffffffu, lt1, 1);
            lt1 += __shfl_xor_sync(0xffffffffu, lt1, 2);
            l0 = l0 * cr0 + lt0;
            l1 = l1 * cr1 + lt1;

#pragma unroll
            for (int n = 0; n < 8; n++) {
                o[n][0] *= cr0; o[n][1] *= cr0;
                o[n][2] *= cr1; o[n][3] *= cr1;
            }

            // ---- O += P V: P fragments straight from registers ----
#pragma unroll
            for (int kb = 0; kb < 4; kb++) {
                uint32_t ap[4];
                ap[0] = f2h2(s[2 * kb][0],     s[2 * kb][1]);
                ap[1] = f2h2(s[2 * kb][2],     s[2 * kb][3]);
                ap[2] = f2h2(s[2 * kb + 1][0], s[2 * kb + 1][1]);
                ap[3] = f2h2(s[2 * kb + 1][2], s[2 * kb + 1][3]);
#pragma unroll
                for (int p = 0; p < 4; p++) {   // dh n-block pairs
                    uint32_t r0, r1, r2, r3;
                    const uint32_t addr =
                        vbase + (uint32_t)((kb * 16 + arow) * AST + p * 16 + acol) * 2;
                    ldm_x4_t(r0, r1, r2, r3, addr);
                    uint32_t bf0[2] = {r0, r1};
                    uint32_t bf1[2] = {r2, r3};
                    mma_f16(o[2 * p],     ap, bf0);
                    mma_f16(o[2 * p + 1], ap, bf1);
                }
            }
        }
    }

    // ---- Normalize + write (layout [b*S+s][h*64+dh]) ----
    const float inv0 = 1.0f / l0;
    const float inv1 = 1.0f / l1;
#pragma unroll
    for (int n = 0; n < 8; n++) {
        const int col = n * 8 + 2 * t;
        *(float2*)(O + base + (size_t)qg0 * D_DIM + col) =
            make_float2(o[n][0] * inv0, o[n][1] * inv0);
        *(float2*)(O + base + (size_t)qg1 * D_DIM + col) =
            make_float2(o[n][2] * inv1, o[n][3] * inv1);
    }
}

// ===========================================================================
extern "C" void kernel_launch(void* const* d_in, const int* in_sizes, int n_in,
                              void* d_out, int out_size) {
    const float* x  = (const float*)d_in[0];
    const float* wq = (const float*)d_in[1];
    const float* wk = (const float*)d_in[2];
    const float* wv = (const float*)d_in[3];
    const float* wo = (const float*)d_in[4];
    float* out = (float*)d_out;

    float *Qp, *Kp, *Vp, *AOp;
    __half *xh, *wqh, *wkh, *wvh, *woh, *aoh;
    cudaGetSymbolAddress((void**)&Qp,  g_Q);
    cudaGetSymbolAddress((void**)&Kp,  g_K);
    cudaGetSymbolAddress((void**)&Vp,  g_V);
    cudaGetSymbolAddress((void**)&AOp, g_AO);
    cudaGetSymbolAddress((void**)&xh,  g_xh);
    cudaGetSymbolAddress((void**)&wqh, g_wqh);
    cudaGetSymbolAddress((void**)&wkh, g_wkh);
    cudaGetSymbolAddress((void**)&wvh, g_wvh);
    cudaGetSymbolAddress((void**)&woh, g_woh);
    cudaGetSymbolAddress((void**)&aoh, g_aoh);

    cudaFuncSetAttribute(gemm_h, cudaFuncAttributeMaxDynamicSharedMemorySize,
                         GEMM_SMEM);

    const int X4 = M_ROWS * D_DIM / 4;   // 2097152
    const int W4 = D_DIM * D_DIM / 4;    // 262144
    f2h_kernel<<<X4 / 256, 256>>>(x,  xh,  X4);
    f2h_kernel<<<W4 / 256, 256>>>(wq, wqh, W4);
    f2h_kernel<<<W4 / 256, 256>>>(wk, wkh, W4);
    f2h_kernel<<<W4 / 256, 256>>>(wv, wvh, W4);
    f2h_kernel<<<W4 / 256, 256>>>(wo, woh, W4);

    dim3 ggrid(D_DIM / 128, M_ROWS / 128);   // (8, 64)
    gemm_h<<<ggrid, 256, GEMM_SMEM>>>(xh, wqh, Qp, M_ROWS, D_DIM, D_DIM);
    gemm_h<<<ggrid, 256, GEMM_SMEM>>>(xh, wkh, Kp, M_ROWS, D_DIM, D_DIM);
    gemm_h<<<ggrid, 256, GEMM_SMEM>>>(xh, wvh, Vp, M_ROWS, D_DIM, D_DIM);

    attn_mma<<<dim3(S_LEN / QT, NB * NH), 256>>>(Qp, Kp, Vp, AOp);

    f2h_kernel<<<X4 / 256, 256>>>(AOp, aoh, X4);
    gemm_h<<<ggrid, 256, GEMM_SMEM>>>(aoh, woh, out, M_ROWS, D_DIM, D_DIM);
}

// round 7
// speedup vs baseline: 9.0831x; 1.0565x over previous
#include <cuda_runtime.h>
#include <cuda_fp16.h>
#include <cstdint>

// Problem constants
#define S_LEN 2048
#define D_DIM 1024
#define NB    4
#define NH    16
#define DHD   64
#define M_ROWS (NB * S_LEN)   // 8192

// Scratch (device globals: allocation-free per harness rules)
__device__ __half g_xh [M_ROWS * D_DIM];
__device__ __half g_wqh[D_DIM * D_DIM];
__device__ __half g_wkh[D_DIM * D_DIM];
__device__ __half g_wvh[D_DIM * D_DIM];
__device__ __half g_woh[D_DIM * D_DIM];
__device__ __half g_Qh [M_ROWS * D_DIM];
__device__ __half g_Kh [M_ROWS * D_DIM];
__device__ __half g_Vh [M_ROWS * D_DIM];
__device__ __half g_aoh[M_ROWS * D_DIM];

// ===========================================================================
// Helpers
// ===========================================================================
__device__ __forceinline__ uint32_t f2h2(float lo, float hi) {
    uint32_t u;
    asm("cvt.rn.f16x2.f32 %0, %1, %2;" : "=r"(u) : "f"(hi), "f"(lo));
    return u;   // low 16 bits = lo
}

__device__ __forceinline__ void mma_f16(float c[4], const uint32_t a[4],
                                        const uint32_t b[2]) {
    asm volatile(
        "mma.sync.aligned.m16n8k16.row.col.f32.f16.f16.f32 "
        "{%0,%1,%2,%3}, {%4,%5,%6,%7}, {%8,%9}, {%0,%1,%2,%3};"
        : "+f"(c[0]), "+f"(c[1]), "+f"(c[2]), "+f"(c[3])
        : "r"(a[0]), "r"(a[1]), "r"(a[2]), "r"(a[3]), "r"(b[0]), "r"(b[1]));
}

__device__ __forceinline__ void ldm_x4(uint32_t& r0, uint32_t& r1,
                                       uint32_t& r2, uint32_t& r3,
                                       uint32_t addr) {
    asm volatile("ldmatrix.sync.aligned.m8n8.x4.shared.b16 {%0,%1,%2,%3}, [%4];"
                 : "=r"(r0), "=r"(r1), "=r"(r2), "=r"(r3) : "r"(addr));
}
__device__ __forceinline__ void ldm_x4_t(uint32_t& r0, uint32_t& r1,
                                         uint32_t& r2, uint32_t& r3,
                                         uint32_t addr) {
    asm volatile("ldmatrix.sync.aligned.m8n8.x4.trans.shared.b16 {%0,%1,%2,%3}, [%4];"
                 : "=r"(r0), "=r"(r1), "=r"(r2), "=r"(r3) : "r"(addr));
}

// ===========================================================================
// fp32 -> fp16 convert (vectorized)
// ===========================================================================
__global__ void __launch_bounds__(256) f2h_kernel(const float* __restrict__ src,
                                                  __half* __restrict__ dst,
                                                  int n4) {
    int i = blockIdx.x * 256 + threadIdx.x;
    if (i < n4) {
        float4 v = ((const float4*)src)[i];
        ((uint2*)dst)[i] = make_uint2(f2h2(v.x, v.y), f2h2(v.z, v.w));
    }
}

// ===========================================================================
// fp16 NT GEMM: C[m,n] = sum_k A[m,k]*B[n,k]; OutT = __half or float.
// 128x128 tile, 256 threads (8 warps 2Mx4N), KC=64, 3-stage cp.async,
// ldmatrix fragments. smem rows: 72 halves (144B).
// ===========================================================================
#define GKC        64
#define GSTR       72
#define GSTAGES    3
#define GTILE_H    (128 * GSTR)
#define GSTAGE_H   (2 * GTILE_H)
#define GEMM_SMEM  (GSTAGES * GSTAGE_H * 2)   // 110592 bytes

template <typename OutT>
__global__ void __launch_bounds__(256) gemm_h(const __half* __restrict__ A,
                                              const __half* __restrict__ B,
                                              OutT* __restrict__ C,
                                              int M, int N, int K) {
    extern __shared__ __half sh[];
    const uint32_t sbase = (uint32_t)__cvta_generic_to_shared(sh);

    const int tid  = threadIdx.x;
    const int lane = tid & 31;
    const int wid  = tid >> 5;
    const int g    = lane >> 2;
    const int t    = lane & 3;
    const int wm   = (wid & 1) * 64;
    const int wn   = (wid >> 1) * 32;
    const int bm   = blockIdx.y * 128;
    const int bn   = blockIdx.x * 128;

    const int arow = (lane & 7) + ((lane & 8) ? 8 : 0);
    const int acol = (lane & 16) ? 8 : 0;
    const int brow = (lane & 7) + ((lane & 16) ? 8 : 0);
    const int bcol = (lane & 8) ? 8 : 0;

    float acc[4][4][4];
#pragma unroll
    for (int i = 0; i < 4; i++)
#pragma unroll
        for (int j = 0; j < 4; j++)
#pragma unroll
            for (int q = 0; q < 4; q++) acc[i][j][q] = 0.0f;

    const int CHUNKS = K / GKC;

    auto issue = [&](int chunk, int st) {
        const __half* Agc = A + (size_t)bm * K + chunk * GKC;
        const __half* Bgc = B + (size_t)bn * K + chunk * GKC;
        const uint32_t sA = sbase + (uint32_t)(st * GSTAGE_H) * 2;
        const uint32_t sB = sA + (uint32_t)GTILE_H * 2;
#pragma unroll
        for (int i = 0; i < 4; i++) {
            const int cid = tid + i * 256;
            const int row = cid >> 3, c16 = cid & 7;
            const __half* ga = Agc + (size_t)row * K + c16 * 8;
            const __half* gb = Bgc + (size_t)row * K + c16 * 8;
            const uint32_t da = sA + (uint32_t)(row * GSTR + c16 * 8) * 2;
            const uint32_t db = sB + (uint32_t)(row * GSTR + c16 * 8) * 2;
            asm volatile("cp.async.cg.shared.global [%0], [%1], 16;" :: "r"(da), "l"(ga));
            asm volatile("cp.async.cg.shared.global [%0], [%1], 16;" :: "r"(db), "l"(gb));
        }
    };

#pragma unroll
    for (int s = 0; s < GSTAGES - 1; s++) {
        issue(s, s);
        asm volatile("cp.async.commit_group;");
    }

    for (int c = 0; c < CHUNKS; c++) {
        const int nc = c + GSTAGES - 1;
        if (nc < CHUNKS) issue(nc, nc % GSTAGES);
        asm volatile("cp.async.commit_group;");
        asm volatile("cp.async.wait_group 2;");
        __syncthreads();

        const int st = c % GSTAGES;
        const uint32_t aBase = sbase + (uint32_t)(st * GSTAGE_H) * 2;
        const uint32_t bBase = aBase + (uint32_t)GTILE_H * 2;

#pragma unroll
        for (int kb = 0; kb < 4; kb++) {
            uint32_t af[4][4], bf[4][2];
#pragma unroll
            for (int im = 0; im < 4; im++) {
                const uint32_t addr =
                    aBase + (uint32_t)((wm + im * 16 + arow) * GSTR + kb * 16 + acol) * 2;
                ldm_x4(af[im][0], af[im][1], af[im][2], af[im][3], addr);
            }
#pragma unroll
            for (int p = 0; p < 2; p++) {
                uint32_t r0, r1, r2, r3;
                const uint32_t addr =
                    bBase + (uint32_t)((wn + p * 16 + brow) * GSTR + kb * 16 + bcol) * 2;
                ldm_x4(r0, r1, r2, r3, addr);
                bf[2 * p][0] = r0; bf[2 * p][1] = r1;
                bf[2 * p + 1][0] = r2; bf[2 * p + 1][1] = r3;
            }
#pragma unroll
            for (int im = 0; im < 4; im++)
#pragma unroll
                for (int jn = 0; jn < 4; jn++)
                    mma_f16(acc[im][jn], af[im], bf[jn]);
        }
        __syncthreads();
    }

#pragma unroll
    for (int im = 0; im < 4; im++) {
#pragma unroll
        for (int jn = 0; jn < 4; jn++) {
            const int row = bm + wm + im * 16 + g;
            const int col = bn + wn + jn * 8 + 2 * t;
            if constexpr (sizeof(OutT) == 2) {
                *(uint32_t*)((__half*)C + (size_t)row * N + col) =
                    f2h2(acc[im][jn][0], acc[im][jn][1]);
                *(uint32_t*)((__half*)C + (size_t)(row + 8) * N + col) =
                    f2h2(acc[im][jn][2], acc[im][jn][3]);
            } else {
                *(float2*)((float*)C + (size_t)row * N + col) =
                    make_float2(acc[im][jn][0], acc[im][jn][1]);
                *(float2*)((float*)C + (size_t)(row + 8) * N + col) =
                    make_float2(acc[im][jn][2], acc[im][jn][3]);
            }
        }
    }
}

// ===========================================================================
// Causal flash attention, fp16 in/out, fp32 accumulate.
//  - Q fragments in registers (ldmatrix once)
//  - K/V tiles double-buffered via cp.async
//  - P accumulator -> A fragment in registers
//  - V read via ldmatrix.trans
// ===========================================================================
#define QT   128
#define KT   64
#define AST  72                             // halves per smem row
// Layout (halves): Q[128*72]=9216, then per stage s: K(s)=9216+s*9216,
// V(s)=K(s)+4608. Total = 9216 + 2*9216 = 27648 halves = 55296 bytes.
#define ATTN_SMEM (27648 * 2)

__global__ void __launch_bounds__(256, 2) attn_mma(const __half* __restrict__ Q,
                                                   const __half* __restrict__ K,
                                                   const __half* __restrict__ V,
                                                   __half* __restrict__ O) {
    extern __shared__ __half ash[];
    const uint32_t sbase = (uint32_t)__cvta_generic_to_shared(ash);
    const uint32_t qbase = sbase;

    const int bh = blockIdx.y;
    const int b  = bh >> 4;
    const int h  = bh & 15;
    const int q0 = blockIdx.x * QT;

    const int tid  = threadIdx.x;
    const int lane = tid & 31;
    const int wid  = tid >> 5;
    const int g    = lane >> 2;
    const int t    = lane & 3;
    const int row0 = wid * 16;

    const int arow = (lane & 7) + ((lane & 8) ? 8 : 0);
    const int acol = (lane & 16) ? 8 : 0;
    const int brow = (lane & 7) + ((lane & 16) ? 8 : 0);
    const int bcol = (lane & 8) ? 8 : 0;

    const size_t base = ((size_t)b * S_LEN) * D_DIM + (size_t)h * DHD;
    const __half* Qg = Q + base;
    const __half* Kg = K + base;
    const __half* Vg = V + base;

    const int ntiles = q0 / KT + 2;   // kv tiles up to and including diagonal

    // ---- Issue K/V tile loads for `tile` into stage tile&1 ----
    auto issueKV = [&](int tile) {
        const int st = tile & 1;
        const uint32_t kB = sbase + (uint32_t)(9216 + st * 9216) * 2;
        const uint32_t vB = kB + (uint32_t)4608 * 2;
        const __half* Kt = Kg + (size_t)(tile * KT) * D_DIM;
        const __half* Vt = Vg + (size_t)(tile * KT) * D_DIM;
#pragma unroll
        for (int i = 0; i < 2; i++) {
            const int cid = tid + i * 256;
            const int row = cid >> 3, c16 = cid & 7;
            const __half* gk = Kt + (size_t)row * D_DIM + c16 * 8;
            const __half* gv = Vt + (size_t)row * D_DIM + c16 * 8;
            const uint32_t dk = kB + (uint32_t)(row * AST + c16 * 8) * 2;
            const uint32_t dv = vB + (uint32_t)(row * AST + c16 * 8) * 2;
            asm volatile("cp.async.cg.shared.global [%0], [%1], 16;" :: "r"(dk), "l"(gk));
            asm volatile("cp.async.cg.shared.global [%0], [%1], 16;" :: "r"(dv), "l"(gv));
        }
        asm volatile("cp.async.commit_group;");
    };

    issueKV(0);

    // ---- Load Q tile (fp16, uint4 copies) ----
#pragma unroll
    for (int i = 0; i < 4; i++) {
        const int cid = tid + i * 256;
        const int row = cid >> 3, c16 = cid & 7;
        uint4 v = *(const uint4*)(Qg + (size_t)(q0 + row) * D_DIM + c16 * 8);
        *(uint4*)(ash + row * AST + c16 * 8) = v;
    }
    __syncthreads();

    // ---- Hoist Q fragments ----
    uint32_t qf[4][4];
#pragma unroll
    for (int kb = 0; kb < 4; kb++) {
        const uint32_t addr =
            qbase + (uint32_t)((row0 + arow) * AST + kb * 16 + acol) * 2;
        ldm_x4(qf[kb][0], qf[kb][1], qf[kb][2], qf[kb][3], addr);
    }

    float m0 = -1e30f, m1 = -1e30f, l0 = 0.0f, l1 = 0.0f;
    float o[8][4];
#pragma unroll
    for (int n = 0; n < 8; n++)
#pragma unroll
        for (int q = 0; q < 4; q++) o[n][q] = 0.0f;

    const float scale = 0.125f;
    const int qg0 = q0 + row0 + g;
    const int qg1 = qg0 + 8;

    for (int tile = 0; tile < ntiles; tile++) {
        const int kv0 = tile * KT;

        __syncthreads();   // all warps done reading buffer (tile+1)&1
        if (tile + 1 < ntiles) issueKV(tile + 1);
        else asm volatile("cp.async.commit_group;");
        asm volatile("cp.async.wait_group 1;");
        __syncthreads();   // stage tile&1 visible to all warps

        const int st = tile & 1;
        const uint32_t kbase = sbase + (uint32_t)(9216 + st * 9216) * 2;
        const uint32_t vbase = kbase + (uint32_t)4608 * 2;

        if (kv0 <= q0 + row0 + 15) {
            // ---- S = Q K^T ----
            float s[8][4];
#pragma unroll
            for (int n = 0; n < 8; n++)
#pragma unroll
                for (int q = 0; q < 4; q++) s[n][q] = 0.0f;

#pragma unroll
            for (int kb = 0; kb < 4; kb++) {
#pragma unroll
                for (int p = 0; p < 4; p++) {
                    uint32_t r0, r1, r2, r3;
                    const uint32_t addr =
                        kbase + (uint32_t)((p * 16 + brow) * AST + kb * 16 + bcol) * 2;
                    ldm_x4(r0, r1, r2, r3, addr);
                    uint32_t bf0[2] = {r0, r1};
                    uint32_t bf1[2] = {r2, r3};
                    mma_f16(s[2 * p],     qf[kb], bf0);
                    mma_f16(s[2 * p + 1], qf[kb], bf1);
                }
            }

            // ---- Scale + causal mask ----
            const bool need_mask = (kv0 + KT - 1) > (q0 + row0);
            if (need_mask) {
#pragma unroll
                for (int n = 0; n < 8; n++) {
#pragma unroll
                    for (int e = 0; e < 2; e++) {
                        const int kg = kv0 + n * 8 + 2 * t + e;
                        s[n][e]     = (kg <= qg0) ? s[n][e] * scale     : -1e30f;
                        s[n][2 + e] = (kg <= qg1) ? s[n][2 + e] * scale : -1e30f;
                    }
                }
            } else {
#pragma unroll
                for (int n = 0; n < 8; n++)
#pragma unroll
                    for (int q = 0; q < 4; q++) s[n][q] *= scale;
            }

            // ---- Online softmax (quad-local reductions) ----
            float mt0 = -1e30f, mt1 = -1e30f;
#pragma unroll
            for (int n = 0; n < 8; n++) {
                mt0 = fmaxf(mt0, fmaxf(s[n][0], s[n][1]));
                mt1 = fmaxf(mt1, fmaxf(s[n][2], s[n][3]));
            }
            mt0 = fmaxf(mt0, __shfl_xor_sync(0xffffffffu, mt0, 1));
            mt0 = fmaxf(mt0, __shfl_xor_sync(0xffffffffu, mt0, 2));
            mt1 = fmaxf(mt1, __shfl_xor_sync(0xffffffffu, mt1, 1));
            mt1 = fmaxf(mt1, __shfl_xor_sync(0xffffffffu, mt1, 2));

            const float mn0 = fmaxf(m0, mt0);
            const float mn1 = fmaxf(m1, mt1);
            const float cr0 = __expf(m0 - mn0);
            const float cr1 = __expf(m1 - mn1);
            m0 = mn0; m1 = mn1;

            float lt0 = 0.0f, lt1 = 0.0f;
#pragma unroll
            for (int n = 0; n < 8; n++) {
                s[n][0] = __expf(s[n][0] - mn0);
                s[n][1] = __expf(s[n][1] - mn0);
                s[n][2] = __expf(s[n][2] - mn1);
                s[n][3] = __expf(s[n][3] - mn1);
                lt0 += s[n][0] + s[n][1];
                lt1 += s[n][2] + s[n][3];
            }
            lt0 += __shfl_xor_sync(0xffffffffu, lt0, 1);
            lt0 += __shfl_xor_sync(0xffffffffu, lt0, 2);
            lt1 += __shfl_xor_sync(0xffffffffu, lt1, 1);
            lt1 += __shfl_xor_sync(0xffffffffu, lt1, 2);
            l0 = l0 * cr0 + lt0;
            l1 = l1 * cr1 + lt1;

#pragma unroll
            for (int n = 0; n < 8; n++) {
                o[n][0] *= cr0; o[n][1] *= cr0;
                o[n][2] *= cr1; o[n][3] *= cr1;
            }

            // ---- O += P V: P fragments straight from registers ----
#pragma unroll
            for (int kb = 0; kb < 4; kb++) {
                uint32_t ap[4];
                ap[0] = f2h2(s[2 * kb][0],     s[2 * kb][1]);
                ap[1] = f2h2(s[2 * kb][2],     s[2 * kb][3]);
                ap[2] = f2h2(s[2 * kb + 1][0], s[2 * kb + 1][1]);
                ap[3] = f2h2(s[2 * kb + 1][2], s[2 * kb + 1][3]);
#pragma unroll
                for (int p = 0; p < 4; p++) {
                    uint32_t r0, r1, r2, r3;
                    const uint32_t addr =
                        vbase + (uint32_t)((kb * 16 + arow) * AST + p * 16 + acol) * 2;
                    ldm_x4_t(r0, r1, r2, r3, addr);
                    uint32_t bf0[2] = {r0, r1};
                    uint32_t bf1[2] = {r2, r3};
                    mma_f16(o[2 * p],     ap, bf0);
                    mma_f16(o[2 * p + 1], ap, bf1);
                }
            }
        }
    }

    // ---- Normalize + write fp16 (layout [b*S+s][h*64+dh]) ----
    const float inv0 = 1.0f / l0;
    const float inv1 = 1.0f / l1;
#pragma unroll
    for (int n = 0; n < 8; n++) {
        const int col = n * 8 + 2 * t;
        *(uint32_t*)(O + base + (size_t)qg0 * D_DIM + col) =
            f2h2(o[n][0] * inv0, o[n][1] * inv0);
        *(uint32_t*)(O + base + (size_t)qg1 * D_DIM + col) =
            f2h2(o[n][2] * inv1, o[n][3] * inv1);
    }
}

// ===========================================================================
extern "C" void kernel_launch(void* const* d_in, const int* in_sizes, int n_in,
                              void* d_out, int out_size) {
    const float* x  = (const float*)d_in[0];
    const float* wq = (const float*)d_in[1];
    const float* wk = (const float*)d_in[2];
    const float* wv = (const float*)d_in[3];
    const float* wo = (const float*)d_in[4];
    float* out = (float*)d_out;

    __half *xh, *wqh, *wkh, *wvh, *woh, *Qh, *Kh, *Vh, *aoh;
    cudaGetSymbolAddress((void**)&xh,  g_xh);
    cudaGetSymbolAddress((void**)&wqh, g_wqh);
    cudaGetSymbolAddress((void**)&wkh, g_wkh);
    cudaGetSymbolAddress((void**)&wvh, g_wvh);
    cudaGetSymbolAddress((void**)&woh, g_woh);
    cudaGetSymbolAddress((void**)&Qh,  g_Qh);
    cudaGetSymbolAddress((void**)&Kh,  g_Kh);
    cudaGetSymbolAddress((void**)&Vh,  g_Vh);
    cudaGetSymbolAddress((void**)&aoh, g_aoh);

    cudaFuncSetAttribute(gemm_h<__half>,
                         cudaFuncAttributeMaxDynamicSharedMemorySize, GEMM_SMEM);
    cudaFuncSetAttribute(gemm_h<float>,
                         cudaFuncAttributeMaxDynamicSharedMemorySize, GEMM_SMEM);
    cudaFuncSetAttribute(attn_mma,
                         cudaFuncAttributeMaxDynamicSharedMemorySize, ATTN_SMEM);

    const int X4 = M_ROWS * D_DIM / 4;
    const int W4 = D_DIM * D_DIM / 4;
    f2h_kernel<<<X4 / 256, 256>>>(x,  xh,  X4);
    f2h_kernel<<<W4 / 256, 256>>>(wq, wqh, W4);
    f2h_kernel<<<W4 / 256, 256>>>(wk, wkh, W4);
    f2h_kernel<<<W4 / 256, 256>>>(wv, wvh, W4);
    f2h_kernel<<<W4 / 256, 256>>>(wo, woh, W4);

    dim3 ggrid(D_DIM / 128, M_ROWS / 128);   // (8, 64)
    gemm_h<__half><<<ggrid, 256, GEMM_SMEM>>>(xh, wqh, Qh, M_ROWS, D_DIM, D_DIM);
    gemm_h<__half><<<ggrid, 256, GEMM_SMEM>>>(xh, wkh, Kh, M_ROWS, D_DIM, D_DIM);
    gemm_h<__half><<<ggrid, 256, GEMM_SMEM>>>(xh, wvh, Vh, M_ROWS, D_DIM, D_DIM);

    attn_mma<<<dim3(S_LEN / QT, NB * NH), 256, ATTN_SMEM>>>(Qh, Kh, Vh, aoh);

    gemm_h<float><<<ggrid, 256, GEMM_SMEM>>>(aoh, woh, out, M_ROWS, D_DIM, D_DIM);
}